// round 14
// baseline (speedup 1.0000x reference)
#include <cuda_runtime.h>

#define NB   1024
#define TT   48
#define NAq  35
#define NMe  18
#define NN   53
#define HH   32
#define CTXD 60
#define THREADS 256
#define WX   64     // xT row stride
#define WD2  68     // h_T / gat_T row stride (conflict-free lane-strided f4)
#define SW   60     // attT/baseT row stride
#define GS   36     // GRU weight row stride ([gate][k] padded)
#define AS   33     // a_src/a_dst row stride (odd -> broadcast rows in distinct banks)

#define CN(n) ((n) < NAq ? (n) : (n) + 5)

typedef unsigned long long u64;

__device__ float g_baseT[NN*SW];

struct __align__(16) SM {
    float attT[NN*SW + 8];      // +8 tail pad
    float h_T[HH*WD2];          // [hd][cn]
    float gat_T[HH*WD2];        // [hd][cn] featf then GAT output
    float xT[6*WX];             // [k][cn]
    float inv[WX];
    float wih_a[96*GS], whh_a[96*GS], wih_m[96*GS], whh_m[96*GS]; // [gate][k] pad GS
    float Wxa[6*HH], Wxm[4*HH], Wua[14*HH], Wum[14*HH];
    float a_src[4][AS], a_dst[4][AS];
    float bih_a[96], bhh_a[96], bih_m[96], bhh_m[96];
    float emb_aqi[158];
    float emb_meo[142];
    float attri[NN*HH];         // [node][hd]
    float srcA[NN], srcM[NN], dstA[NN], dstM[NN];
    float ctxsA[NN], ctxsM[NN], ctxdA[NN], ctxdM[NN];
    int   exa[NAq*4];
    int   exm[NMe*5];
};

__device__ __forceinline__ u64 pk2(float lo, float hi) {
    u64 r; asm("mov.b64 %0,{%1,%2};" : "=l"(r) : "f"(lo), "f"(hi)); return r;
}
__device__ __forceinline__ u64 dup2(float v) { return pk2(v, v); }
__device__ __forceinline__ float2 up2(u64 a) {
    float2 r; asm("mov.b64 {%0,%1},%2;" : "=f"(r.x), "=f"(r.y) : "l"(a)); return r;
}
__device__ __forceinline__ void fma2(u64& d, u64 a, u64 b) {
    asm("fma.rn.f32x2 %0,%1,%2,%0;" : "+l"(d) : "l"(a), "l"(b));
}
__device__ __forceinline__ u64 mul2(u64 a, u64 b) {
    u64 r; asm("mul.rn.f32x2 %0,%1,%2;" : "=l"(r) : "l"(a), "l"(b)); return r;
}
__device__ __forceinline__ float sigf(float x) {
    return __fdividef(1.f, 1.f + __expf(-x));
}
__device__ __forceinline__ float tanhf_fast(float x) {
    return 2.f * sigf(2.f * x) - 1.f;
}

__global__ void base_kernel(const float* __restrict__ adj, const float* __restrict__ adjn,
                            const float* __restrict__ a_aa, const float* __restrict__ a_am,
                            const float* __restrict__ a_ma, const float* __restrict__ a_mm)
{
    float aL[4] = {a_aa[184], a_am[184], a_ma[184], a_mm[184]};
    int idx = blockIdx.x * blockDim.x + threadIdx.x;
    for (int p = idx; p < NN*SW; p += gridDim.x * blockDim.x) {
        int j = p / SW, cn = p % SW;
        bool valid = (cn < NAq) || (cn >= 40 && cn < 58);
        float v = -1e30f;
        if (valid) {
            int i = (cn < NAq) ? cn : cn - 5;
            int c = ((i < NAq) ? 0 : 2) + ((j < NAq) ? 0 : 1);
            v = (adj[i*NN+j] > 0.f) ? adjn[i*NN+j]*aL[c] : -1e30f;
        }
        g_baseT[p] = v;
    }
}

__global__ __launch_bounds__(THREADS, 2)
void chgat_gru_kernel(
    const float* __restrict__ X_aqi, const float* __restrict__ X_meo,
    const float* __restrict__ ctx,
    const float* __restrict__ e_ai,  const float* __restrict__ e_amo,
    const float* __restrict__ e_awd, const float* __restrict__ e_ahr,
    const float* __restrict__ e_mw,  const float* __restrict__ e_mi,
    const float* __restrict__ e_mmo, const float* __restrict__ e_mwd,
    const float* __restrict__ e_mhr,
    const float* __restrict__ Wxa,   const float* __restrict__ Wxm,
    const float* __restrict__ Wua,   const float* __restrict__ Wum,
    const float* __restrict__ a_aa,  const float* __restrict__ a_am,
    const float* __restrict__ a_ma,  const float* __restrict__ a_mm,
    const float* __restrict__ gaw_ih, const float* __restrict__ gaw_hh,
    const float* __restrict__ gab_ih, const float* __restrict__ gab_hh,
    const float* __restrict__ gmw_ih, const float* __restrict__ gmw_hh,
    const float* __restrict__ gmb_ih, const float* __restrict__ gmb_hh,
    const int* __restrict__ Xa_ex,   const int* __restrict__ Xm_ex,
    float* __restrict__ out)
{
    extern __shared__ char smraw[];
    SM& s = *reinterpret_cast<SM*>(smraw);

    const int tid  = threadIdx.x;
    const int b    = blockIdx.x;
    const int lane = tid & 31;
    const int wid  = tid >> 5;

    // ---------- one-time setup ----------
    for (int i = tid; i < 6*HH;  i += THREADS) s.Wxa[i] = Wxa[i];
    for (int i = tid; i < 4*HH;  i += THREADS) s.Wxm[i] = Wxm[i];
    for (int i = tid; i < 14*HH; i += THREADS) { s.Wua[i] = Wua[i]; s.Wum[i] = Wum[i]; }
    for (int i = tid; i < 96*HH; i += THREADS) {
        int g = i >> 5, k = i & 31;
        s.wih_a[g*GS+k] = gaw_ih[i]; s.whh_a[g*GS+k] = gaw_hh[i];
        s.wih_m[g*GS+k] = gmw_ih[i]; s.whh_m[g*GS+k] = gmw_hh[i];
    }
    for (int i = tid; i < 96; i += THREADS) {
        s.bih_a[i] = gab_ih[i]; s.bhh_a[i] = gab_hh[i];
        s.bih_m[i] = gmb_ih[i]; s.bhh_m[i] = gmb_hh[i];
    }
    for (int i = tid; i < 4*HH; i += THREADS) {
        int c = i >> 5, k = i & 31;
        const float* a = (c==0)?a_aa:(c==1)?a_am:(c==2)?a_ma:a_mm;
        s.a_src[c][k] = a[k];
        s.a_dst[c][k] = a[92+k];
    }
    for (int i = tid; i < 70; i += THREADS) s.emb_aqi[i]      = e_ai[i];
    for (int i = tid; i < 26; i += THREADS) s.emb_aqi[70+i]   = e_amo[i];
    for (int i = tid; i < 14; i += THREADS) s.emb_aqi[96+i]   = e_awd[i];
    for (int i = tid; i < 48; i += THREADS) s.emb_aqi[110+i]  = e_ahr[i];
    for (int i = tid; i < 18; i += THREADS) s.emb_meo[i]      = e_mw[i];
    for (int i = tid; i < 36; i += THREADS) s.emb_meo[18+i]   = e_mi[i];
    for (int i = tid; i < 26; i += THREADS) s.emb_meo[54+i]   = e_mmo[i];
    for (int i = tid; i < 14; i += THREADS) s.emb_meo[80+i]   = e_mwd[i];
    for (int i = tid; i < 48; i += THREADS) s.emb_meo[94+i]   = e_mhr[i];
    for (int i = tid; i < HH*WD2; i += THREADS) s.h_T[i] = 0.f;
    for (int i = tid; i < 6*WX; i += THREADS) s.xT[i] = 0.f;
    // zero attT + inv fully ONCE (pad columns never rewritten afterwards)
    for (int i = tid; i < NN*SW + 8; i += THREADS) s.attT[i] = 0.f;
    for (int i = tid; i < WX; i += THREADS) s.inv[i] = 0.f;
    __syncthreads();

    // context dots (role x node), once
    for (int p = tid; p < 4*NN; p += THREADS) {
        int n = p % NN, role = p / NN;
        int c;
        if (role == 0)      c = (n<NAq)?0:2;
        else if (role == 1) c = (n<NAq)?1:3;
        else if (role == 2) c = (n<NAq)?0:1;
        else                c = (n<NAq)?2:3;
        const float* a = (c==0)?a_aa:(c==1)?a_am:(c==2)?a_ma:a_mm;
        const float* w = (role < 2) ? (a + 32) : (a + 124);
        float acc = 0.f;
        #pragma unroll 4
        for (int k = 0; k < CTXD; k++) acc += ctx[n*CTXD+k]*w[k];
        if (role == 0)      s.ctxsA[n] = acc;
        else if (role == 1) s.ctxsM[n] = acc;
        else if (role == 2) s.ctxdA[n] = acc;
        else                s.ctxdM[n] = acc;
    }
    __syncthreads();

    const int  cn0 = wid * 8;
    const bool isA = (wid < 5);
    const int  npr = (wid==4) ? 2 : ((wid==7) ? 1 : 4);   // valid node-pairs in tile
    const float* WI = isA ? s.wih_a : s.wih_m;
    const float* WH = isA ? s.whh_a : s.whh_m;
    const float* BI = isA ? s.bih_a : s.bih_m;
    const float* BH = isA ? s.bhh_a : s.bhh_m;
    const float b_ir = BI[lane], b_iz = BI[32+lane], b_in = BI[64+lane];
    const float b_hr = BH[lane], b_hz = BH[32+lane], b_hn = BH[64+lane];
    const int sm_cn  = cn0 + (lane >> 2);
    const int sm_sub = lane & 3;
    const bool sm_valid = (sm_cn < NAq) || (sm_cn >= 40 && sm_cn < 58);

    // ---------- timestep loop: 3 CTA barriers per step ----------
    for (int t = 0; t < TT; t++) {
        // p0: load + transpose raw features (dest-coalesced conflict-free stores)
        {
            const float* gx = X_aqi + (size_t)(b*TT + t)*NAq*6;
            for (int i = tid; i < NAq*6; i += THREADS) {
                int k = i / NAq, n = i % NAq;
                s.xT[k*WX + n] = gx[n*6 + k];
            }
            const float* gm = X_meo + (size_t)(b*TT + t)*NMe*4;
            for (int i = tid; i < NMe*4; i += THREADS) {
                int k = i / NMe, m = i % NMe;
                s.xT[k*WX + 40 + m] = gm[m*4 + k];
            }
            const int* ga = Xa_ex + (size_t)(b*TT + t)*NAq*4;
            for (int i = tid; i < NAq*4; i += THREADS) s.exa[i] = ga[i];
            const int* gme = Xm_ex + (size_t)(b*TT + t)*NMe*5;
            for (int i = tid; i < NMe*5; i += THREADS) s.exm[i] = gme[i];
        }
        __syncthreads();   // B1

        // p1: attri + featf, one 8-node tile per warp, f32x2 packed
        {
            u64 av[4] = {0,0,0,0}, fv[4] = {0,0,0,0};
            if (isA) {
                #pragma unroll
                for (int k = 0; k < 6; k++) {
                    ulonglong2 xa = *(const ulonglong2*)(s.xT + k*WX + cn0);
                    ulonglong2 xb = *(const ulonglong2*)(s.xT + k*WX + cn0 + 4);
                    u64 wa = dup2(s.Wxa[k*HH+lane]);
                    u64 wu = dup2(s.Wua[k*HH+lane]);
                    fma2(av[0], xa.x, wa); fma2(av[1], xa.y, wa);
                    fma2(av[2], xb.x, wa); fma2(av[3], xb.y, wa);
                    fma2(fv[0], xa.x, wu); fma2(fv[1], xa.y, wu);
                    fma2(fv[2], xb.x, wu); fma2(fv[3], xb.y, wu);
                }
                const int offs[4] = {0, 35, 48, 55};
                #pragma unroll
                for (int e = 0; e < 4; e++) {
                    u64 wA = dup2(s.Wua[(6+2*e)*HH+lane]);
                    u64 wB = dup2(s.Wua[(7+2*e)*HH+lane]);
                    #pragma unroll
                    for (int pr = 0; pr < 4; pr++) {
                        int n0 = cn0 + 2*pr, n1 = n0 + 1;
                        int i0 = (n0 < NAq) ? s.exa[n0*4+e] : 0;
                        int i1 = (n1 < NAq) ? s.exa[n1*4+e] : 0;
                        float2 em0 = *(const float2*)(s.emb_aqi + (offs[e]+i0)*2);
                        float2 em1 = *(const float2*)(s.emb_aqi + (offs[e]+i1)*2);
                        fma2(fv[pr], pk2(em0.x, em1.x), wA);
                        fma2(fv[pr], pk2(em0.y, em1.y), wB);
                    }
                }
                #pragma unroll
                for (int pr = 0; pr < 4; pr++) {
                    float2 a2 = up2(av[pr]);
                    int n0 = cn0 + 2*pr;
                    if (n0   < NAq) s.attri[n0*HH + lane]     = a2.x;
                    if (n0+1 < NAq) s.attri[(n0+1)*HH + lane] = a2.y;
                }
            } else {
                #pragma unroll
                for (int k = 0; k < 4; k++) {
                    ulonglong2 xa = *(const ulonglong2*)(s.xT + k*WX + cn0);
                    ulonglong2 xb = *(const ulonglong2*)(s.xT + k*WX + cn0 + 4);
                    u64 wa = dup2(s.Wxm[k*HH+lane]);
                    u64 wu = dup2(s.Wum[k*HH+lane]);
                    fma2(av[0], xa.x, wa); fma2(av[1], xa.y, wa);
                    fma2(av[2], xb.x, wa); fma2(av[3], xb.y, wa);
                    fma2(fv[0], xa.x, wu); fma2(fv[1], xa.y, wu);
                    fma2(fv[2], xb.x, wu); fma2(fv[3], xb.y, wu);
                }
                const int offs[5] = {0, 9, 27, 40, 47};
                #pragma unroll
                for (int e = 0; e < 5; e++) {
                    u64 wA = dup2(s.Wum[(4+2*e)*HH+lane]);
                    u64 wB = dup2(s.Wum[(5+2*e)*HH+lane]);
                    #pragma unroll
                    for (int pr = 0; pr < 4; pr++) {
                        int c0 = cn0 + 2*pr, c1 = c0 + 1;
                        int i0 = (c0 <= 57) ? s.exm[(c0-40)*5+e] : 0;
                        int i1 = (c1 <= 57) ? s.exm[(c1-40)*5+e] : 0;
                        float2 em0 = *(const float2*)(s.emb_meo + (offs[e]+i0)*2);
                        float2 em1 = *(const float2*)(s.emb_meo + (offs[e]+i1)*2);
                        fma2(fv[pr], pk2(em0.x, em1.x), wA);
                        fma2(fv[pr], pk2(em0.y, em1.y), wB);
                    }
                }
                #pragma unroll
                for (int pr = 0; pr < 4; pr++) {
                    float2 a2 = up2(av[pr]);
                    int c0 = cn0 + 2*pr;
                    if (c0   <= 57) s.attri[(c0-5)*HH + lane] = a2.x;
                    if (c0+1 <= 57) s.attri[(c0-4)*HH + lane] = a2.y;
                }
            }
            *(ulonglong2*)(s.gat_T + lane*WD2 + cn0)     = make_ulonglong2(fv[0], fv[1]);
            *(ulonglong2*)(s.gat_T + lane*WD2 + cn0 + 4) = make_ulonglong2(fv[2], fv[3]);
        }
        __syncthreads();   // B2

        // p2: src/dst projections (role x column); padded weight rows -> no bank conflict
        {
            int role = tid >> 6, q = tid & 63;
            bool valid = (q < NAq) || (q >= 40 && q < 58);
            int n = (q < NAq) ? q : q - 5;
            int c; float acc; const float* w;
            bool nA = q < NAq;
            if (role == 0)      { c = nA?0:2; w = s.a_src[c]; acc = valid ? s.ctxsA[n] : 0.f; }
            else if (role == 1) { c = nA?1:3; w = s.a_src[c]; acc = valid ? s.ctxsM[n] : 0.f; }
            else if (role == 2) { c = nA?0:1; w = s.a_dst[c]; acc = valid ? s.ctxdA[n] : 0.f; }
            else                { c = nA?2:3; w = s.a_dst[c]; acc = valid ? s.ctxdM[n] : 0.f; }
            #pragma unroll 8
            for (int k = 0; k < HH; k++) acc += s.gat_T[k*WD2 + (q < 58 ? q : 0)] * w[k];
            if (valid) {
                if (role == 0)      s.srcA[n] = acc;
                else if (role == 1) s.srcM[n] = acc;
                else if (role == 2) s.dstA[n] = acc;
                else                s.dstM[n] = acc;
            }
        }
        __syncthreads();   // B3 — everything below is warp-private

        // p3/4: logits + exp + sum (valid columns only; pads stay zero from init)
        {
            float sum = 0.f;
            if (sm_valid) {
                int i = (sm_cn < NAq) ? sm_cn : sm_cn - 5;
                float sAv = s.srcA[i], sMv = s.srcM[i];
                const float* dp = (i < NAq) ? s.dstA : s.dstM;
                for (int j = sm_sub; j < NN; j += 4) {
                    float x = ((j < NAq) ? sAv : sMv) + dp[j] + __ldg(g_baseT + j*SW + sm_cn);
                    x = (x >= 0.f) ? x : 0.2f*x;
                    float v = __expf(fminf(x, 60.f));
                    s.attT[j*SW+sm_cn] = v;
                    sum += v;
                }
            }
            sum += __shfl_xor_sync(0xffffffffu, sum, 1);
            sum += __shfl_xor_sync(0xffffffffu, sum, 2);
            if (sm_sub == 0 && sm_valid) s.inv[sm_cn] = __fdividef(1.f, sum);
        }
        __syncwarp();

        // p5: GAT output (att @ attri, f32x2), same-warp tile, pair-guarded
        {
            u64 acc[4] = {0,0,0,0};
            #pragma unroll 4
            for (int j = 0; j < NN; j++) {
                u64 ap = dup2(s.attri[j*HH + lane]);
                ulonglong2 t0 = *(const ulonglong2*)(s.attT + j*SW + cn0);
                fma2(acc[0], t0.x, ap);
                if (npr > 1) fma2(acc[1], t0.y, ap);
                if (npr > 2) {
                    ulonglong2 t1 = *(const ulonglong2*)(s.attT + j*SW + cn0 + 4);
                    fma2(acc[2], t1.x, ap); fma2(acc[3], t1.y, ap);
                }
            }
            float4 iv0 = *(const float4*)(s.inv + cn0);
            acc[0] = mul2(acc[0], pk2(iv0.x, iv0.y));
            acc[1] = mul2(acc[1], pk2(iv0.z, iv0.w));
            *(ulonglong2*)(s.gat_T + lane*WD2 + cn0) = make_ulonglong2(acc[0], acc[1]);
            if (npr > 2) {
                float4 iv1 = *(const float4*)(s.inv + cn0 + 4);
                acc[2] = mul2(acc[2], pk2(iv1.x, iv1.y));
                acc[3] = mul2(acc[3], pk2(iv1.z, iv1.w));
                *(ulonglong2*)(s.gat_T + lane*WD2 + cn0 + 4) = make_ulonglong2(acc[2], acc[3]);
            }
        }
        __syncwarp();

        // p6: GRU, same tile, f32x2; weights via per-lane float4 rows
        {
            u64 gr[4]={0,0,0,0}, gz[4]={0,0,0,0}, gn[4]={0,0,0,0};
            u64 hr[4]={0,0,0,0}, hz[4]={0,0,0,0}, hn[4]={0,0,0,0};
            #pragma unroll
            for (int kc = 0; kc < 8; kc++) {
                float4 W0 = *(const float4*)(WI + lane*GS + 4*kc);
                float4 W1 = *(const float4*)(WI + (32+lane)*GS + 4*kc);
                float4 W2 = *(const float4*)(WI + (64+lane)*GS + 4*kc);
                float4 V0 = *(const float4*)(WH + lane*GS + 4*kc);
                float4 V1 = *(const float4*)(WH + (32+lane)*GS + 4*kc);
                float4 V2 = *(const float4*)(WH + (64+lane)*GS + 4*kc);
                const float* w0p = (const float*)&W0;
                const float* w1p = (const float*)&W1;
                const float* w2p = (const float*)&W2;
                const float* v0p = (const float*)&V0;
                const float* v1p = (const float*)&V1;
                const float* v2p = (const float*)&V2;
                #pragma unroll
                for (int kk = 0; kk < 4; kk++) {
                    int k = 4*kc + kk;
                    ulonglong2 x0 = *(const ulonglong2*)(s.gat_T + k*WD2 + cn0);
                    ulonglong2 x1 = *(const ulonglong2*)(s.gat_T + k*WD2 + cn0 + 4);
                    ulonglong2 h0 = *(const ulonglong2*)(s.h_T  + k*WD2 + cn0);
                    ulonglong2 h1 = *(const ulonglong2*)(s.h_T  + k*WD2 + cn0 + 4);
                    u64 w0 = dup2(w0p[kk]);
                    u64 w1 = dup2(w1p[kk]);
                    u64 w2 = dup2(w2p[kk]);
                    u64 v0 = dup2(v0p[kk]);
                    u64 v1 = dup2(v1p[kk]);
                    u64 v2 = dup2(v2p[kk]);
                    fma2(gr[0], x0.x, w0); fma2(gr[1], x0.y, w0);
                    fma2(gr[2], x1.x, w0); fma2(gr[3], x1.y, w0);
                    fma2(gz[0], x0.x, w1); fma2(gz[1], x0.y, w1);
                    fma2(gz[2], x1.x, w1); fma2(gz[3], x1.y, w1);
                    fma2(gn[0], x0.x, w2); fma2(gn[1], x0.y, w2);
                    fma2(gn[2], x1.x, w2); fma2(gn[3], x1.y, w2);
                    fma2(hr[0], h0.x, v0); fma2(hr[1], h0.y, v0);
                    fma2(hr[2], h1.x, v0); fma2(hr[3], h1.y, v0);
                    fma2(hz[0], h0.x, v1); fma2(hz[1], h0.y, v1);
                    fma2(hz[2], h1.x, v1); fma2(hz[3], h1.y, v1);
                    fma2(hn[0], h0.x, v2); fma2(hn[1], h0.y, v2);
                    fma2(hn[2], h1.x, v2); fma2(hn[3], h1.y, v2);
                }
            }
            ulonglong2 ho0 = *(const ulonglong2*)(s.h_T + lane*WD2 + cn0);
            ulonglong2 ho1 = *(const ulonglong2*)(s.h_T + lane*WD2 + cn0 + 4);
            u64 hop[4] = {ho0.x, ho0.y, ho1.x, ho1.y};
            u64 res[4];
            #pragma unroll
            for (int p = 0; p < 4; p++) {
                float2 R = up2(gr[p]), Z = up2(gz[p]), Nn = up2(gn[p]);
                float2 HR = up2(hr[p]), HZ = up2(hz[p]), HN = up2(hn[p]);
                float2 HO = up2(hop[p]);
                float r0 = sigf(R.x + b_ir + HR.x + b_hr);
                float z0 = sigf(Z.x + b_iz + HZ.x + b_hz);
                float n0 = tanhf_fast(Nn.x + b_in + r0*(HN.x + b_hn));
                float o0 = (1.f - z0)*n0 + z0*HO.x;
                float r1 = sigf(R.y + b_ir + HR.y + b_hr);
                float z1 = sigf(Z.y + b_iz + HZ.y + b_hz);
                float n1 = tanhf_fast(Nn.y + b_in + r1*(HN.y + b_hn));
                float o1 = (1.f - z1)*n1 + z1*HO.y;
                res[p] = pk2(o0, o1);
            }
            __syncwarp();
            *(ulonglong2*)(s.h_T + lane*WD2 + cn0)     = make_ulonglong2(res[0], res[1]);
            *(ulonglong2*)(s.h_T + lane*WD2 + cn0 + 4) = make_ulonglong2(res[2], res[3]);
        }
    }

    // ---------- output ----------
    __syncthreads();
    for (int p = tid; p < NN*HH; p += THREADS) {
        int n = p >> 5, hd = p & 31;
        float v = s.h_T[hd*WD2 + CN(n)];
        if (n < NAq) out[((size_t)b*NAq + n)*HH + hd] = v;
        else         out[(size_t)NB*NAq*HH + ((size_t)b*NMe + (n-NAq))*HH + hd] = v;
    }
}

extern "C" void kernel_launch(void* const* d_in, const int* in_sizes, int n_in,
                              void* d_out, int out_size)
{
    (void)in_sizes; (void)n_in; (void)out_size;
    base_kernel<<<8, 256>>>(
        (const float*)d_in[3],  (const float*)d_in[4],
        (const float*)d_in[18], (const float*)d_in[19],
        (const float*)d_in[20], (const float*)d_in[21]);
    cudaFuncSetAttribute(chgat_gru_kernel,
                         cudaFuncAttributeMaxDynamicSharedMemorySize,
                         (int)sizeof(SM));
    chgat_gru_kernel<<<NB, THREADS, sizeof(SM)>>>(
        (const float*)d_in[0],  (const float*)d_in[1],
        (const float*)d_in[2],
        (const float*)d_in[5],  (const float*)d_in[6],
        (const float*)d_in[7],  (const float*)d_in[8],
        (const float*)d_in[9],  (const float*)d_in[10],
        (const float*)d_in[11], (const float*)d_in[12],
        (const float*)d_in[13],
        (const float*)d_in[14], (const float*)d_in[15],
        (const float*)d_in[16], (const float*)d_in[17],
        (const float*)d_in[18], (const float*)d_in[19],
        (const float*)d_in[20], (const float*)d_in[21],
        (const float*)d_in[22], (const float*)d_in[23],
        (const float*)d_in[24], (const float*)d_in[25],
        (const float*)d_in[26], (const float*)d_in[27],
        (const float*)d_in[28], (const float*)d_in[29],
        (const int*)d_in[30],   (const int*)d_in[31],
        (float*)d_out);
}

// round 15
// speedup vs baseline: 1.1200x; 1.1200x over previous
#include <cuda_runtime.h>

#define NB   1024
#define TT   48
#define NAq  35
#define NMe  18
#define NN   53
#define HH   32
#define CTXD 60
#define THREADS 256
#define WX   64     // xT row stride
#define WD2  68     // h_T / gat_T row stride
#define SW   60     // attT/baseT row stride
#define GS   36     // GRU weight row stride ([gate][k] padded)
#define AS   33     // a_src/a_dst row stride (odd -> broadcast rows in distinct banks)

#define CN(n) ((n) < NAq ? (n) : (n) + 5)

typedef unsigned long long u64;

__device__ float g_baseT[NN*SW];

struct __align__(16) SM {
    float attT[NN*SW + 8];      // +8 tail pad
    float h_T[HH*WD2];          // [hd][cn]
    float gat_T[HH*WD2];        // [hd][cn] featf then GAT output
    float xT[6*WX];             // [k][cn]
    float inv[WX];
    float wih_a[96*GS], whh_a[96*GS], wih_m[96*GS], whh_m[96*GS]; // [gate][k] pad GS
    float Wxa[6*HH], Wxm[4*HH], Wua[14*HH], Wum[14*HH];
    float a_src[4][AS], a_dst[4][AS];
    float bih_a[96], bhh_a[96], bih_m[96], bhh_m[96];
    float emb_aqi[158];
    float emb_meo[142];
    float attri[NN*HH];         // [node][hd]
    float srcA[NN], srcM[NN], dstA[NN], dstM[NN];
    float ctxsA[NN], ctxsM[NN], ctxdA[NN], ctxdM[NN];
    int   exa[NAq*4];
    int   exm[NMe*5];
};

__device__ __forceinline__ u64 pk2(float lo, float hi) {
    u64 r; asm("mov.b64 %0,{%1,%2};" : "=l"(r) : "f"(lo), "f"(hi)); return r;
}
__device__ __forceinline__ u64 dup2(float v) { return pk2(v, v); }
__device__ __forceinline__ float2 up2(u64 a) {
    float2 r; asm("mov.b64 {%0,%1},%2;" : "=f"(r.x), "=f"(r.y) : "l"(a)); return r;
}
__device__ __forceinline__ void fma2(u64& d, u64 a, u64 b) {
    asm("fma.rn.f32x2 %0,%1,%2,%0;" : "+l"(d) : "l"(a), "l"(b));
}
__device__ __forceinline__ u64 mul2(u64 a, u64 b) {
    u64 r; asm("mul.rn.f32x2 %0,%1,%2;" : "=l"(r) : "l"(a), "l"(b)); return r;
}
__device__ __forceinline__ float sigf(float x) {
    return __fdividef(1.f, 1.f + __expf(-x));
}
__device__ __forceinline__ float tanhf_fast(float x) {
    return 2.f * sigf(2.f * x) - 1.f;
}

__global__ void base_kernel(const float* __restrict__ adj, const float* __restrict__ adjn,
                            const float* __restrict__ a_aa, const float* __restrict__ a_am,
                            const float* __restrict__ a_ma, const float* __restrict__ a_mm)
{
    float aL[4] = {a_aa[184], a_am[184], a_ma[184], a_mm[184]};
    int idx = blockIdx.x * blockDim.x + threadIdx.x;
    for (int p = idx; p < NN*SW; p += gridDim.x * blockDim.x) {
        int j = p / SW, cn = p % SW;
        bool valid = (cn < NAq) || (cn >= 40 && cn < 58);
        float v = -1e30f;
        if (valid) {
            int i = (cn < NAq) ? cn : cn - 5;
            int c = ((i < NAq) ? 0 : 2) + ((j < NAq) ? 0 : 1);
            v = (adj[i*NN+j] > 0.f) ? adjn[i*NN+j]*aL[c] : -1e30f;
        }
        g_baseT[p] = v;
    }
}

__global__ __launch_bounds__(THREADS, 2)
void chgat_gru_kernel(
    const float* __restrict__ X_aqi, const float* __restrict__ X_meo,
    const float* __restrict__ ctx,
    const float* __restrict__ e_ai,  const float* __restrict__ e_amo,
    const float* __restrict__ e_awd, const float* __restrict__ e_ahr,
    const float* __restrict__ e_mw,  const float* __restrict__ e_mi,
    const float* __restrict__ e_mmo, const float* __restrict__ e_mwd,
    const float* __restrict__ e_mhr,
    const float* __restrict__ Wxa,   const float* __restrict__ Wxm,
    const float* __restrict__ Wua,   const float* __restrict__ Wum,
    const float* __restrict__ a_aa,  const float* __restrict__ a_am,
    const float* __restrict__ a_ma,  const float* __restrict__ a_mm,
    const float* __restrict__ gaw_ih, const float* __restrict__ gaw_hh,
    const float* __restrict__ gab_ih, const float* __restrict__ gab_hh,
    const float* __restrict__ gmw_ih, const float* __restrict__ gmw_hh,
    const float* __restrict__ gmb_ih, const float* __restrict__ gmb_hh,
    const int* __restrict__ Xa_ex,   const int* __restrict__ Xm_ex,
    float* __restrict__ out)
{
    extern __shared__ char smraw[];
    SM& s = *reinterpret_cast<SM*>(smraw);

    const int tid  = threadIdx.x;
    const int b    = blockIdx.x;
    const int lane = tid & 31;
    const int wid  = tid >> 5;

    // ---------- one-time setup ----------
    for (int i = tid; i < 6*HH;  i += THREADS) s.Wxa[i] = Wxa[i];
    for (int i = tid; i < 4*HH;  i += THREADS) s.Wxm[i] = Wxm[i];
    for (int i = tid; i < 14*HH; i += THREADS) { s.Wua[i] = Wua[i]; s.Wum[i] = Wum[i]; }
    for (int i = tid; i < 96*HH; i += THREADS) {
        int g = i >> 5, k = i & 31;
        s.wih_a[g*GS+k] = gaw_ih[i]; s.whh_a[g*GS+k] = gaw_hh[i];
        s.wih_m[g*GS+k] = gmw_ih[i]; s.whh_m[g*GS+k] = gmw_hh[i];
    }
    for (int i = tid; i < 96; i += THREADS) {
        s.bih_a[i] = gab_ih[i]; s.bhh_a[i] = gab_hh[i];
        s.bih_m[i] = gmb_ih[i]; s.bhh_m[i] = gmb_hh[i];
    }
    for (int i = tid; i < 4*HH; i += THREADS) {
        int c = i >> 5, k = i & 31;
        const float* a = (c==0)?a_aa:(c==1)?a_am:(c==2)?a_ma:a_mm;
        s.a_src[c][k] = a[k];
        s.a_dst[c][k] = a[92+k];
    }
    for (int i = tid; i < 70; i += THREADS) s.emb_aqi[i]      = e_ai[i];
    for (int i = tid; i < 26; i += THREADS) s.emb_aqi[70+i]   = e_amo[i];
    for (int i = tid; i < 14; i += THREADS) s.emb_aqi[96+i]   = e_awd[i];
    for (int i = tid; i < 48; i += THREADS) s.emb_aqi[110+i]  = e_ahr[i];
    for (int i = tid; i < 18; i += THREADS) s.emb_meo[i]      = e_mw[i];
    for (int i = tid; i < 36; i += THREADS) s.emb_meo[18+i]   = e_mi[i];
    for (int i = tid; i < 26; i += THREADS) s.emb_meo[54+i]   = e_mmo[i];
    for (int i = tid; i < 14; i += THREADS) s.emb_meo[80+i]   = e_mwd[i];
    for (int i = tid; i < 48; i += THREADS) s.emb_meo[94+i]   = e_mhr[i];
    for (int i = tid; i < HH*WD2; i += THREADS) s.h_T[i] = 0.f;
    for (int i = tid; i < 6*WX; i += THREADS) s.xT[i] = 0.f;
    // zero attT + inv fully ONCE (pad columns never rewritten afterwards)
    for (int i = tid; i < NN*SW + 8; i += THREADS) s.attT[i] = 0.f;
    for (int i = tid; i < WX; i += THREADS) s.inv[i] = 0.f;
    __syncthreads();

    // context dots (role x node), once
    for (int p = tid; p < 4*NN; p += THREADS) {
        int n = p % NN, role = p / NN;
        int c;
        if (role == 0)      c = (n<NAq)?0:2;
        else if (role == 1) c = (n<NAq)?1:3;
        else if (role == 2) c = (n<NAq)?0:1;
        else                c = (n<NAq)?2:3;
        const float* a = (c==0)?a_aa:(c==1)?a_am:(c==2)?a_ma:a_mm;
        const float* w = (role < 2) ? (a + 32) : (a + 124);
        float acc = 0.f;
        #pragma unroll 4
        for (int k = 0; k < CTXD; k++) acc += ctx[n*CTXD+k]*w[k];
        if (role == 0)      s.ctxsA[n] = acc;
        else if (role == 1) s.ctxsM[n] = acc;
        else if (role == 2) s.ctxdA[n] = acc;
        else                s.ctxdM[n] = acc;
    }
    __syncthreads();

    const int  cn0 = wid * 8;
    const bool isA = (wid < 5);
    const float* WI = isA ? s.wih_a : s.wih_m;
    const float* WH = isA ? s.whh_a : s.whh_m;
    const float* BI = isA ? s.bih_a : s.bih_m;
    const float* BH = isA ? s.bhh_a : s.bhh_m;
    const float b_ir = BI[lane], b_iz = BI[32+lane], b_in = BI[64+lane];
    const float b_hr = BH[lane], b_hz = BH[32+lane], b_hn = BH[64+lane];
    const int sm_cn  = cn0 + (lane >> 2);
    const int sm_sub = lane & 3;
    const bool sm_valid = (sm_cn < NAq) || (sm_cn >= 40 && sm_cn < 58);

    // ---------- timestep loop: 3 CTA barriers per step ----------
    for (int t = 0; t < TT; t++) {
        // p0: load (coalesced reads) + transpose raw features
        {
            const float* gx = X_aqi + (size_t)(b*TT + t)*NAq*6;
            for (int i = tid; i < NAq*6; i += THREADS) {
                int n = i/6, k = i%6;
                s.xT[k*WX + n] = gx[i];
            }
            const float* gm = X_meo + (size_t)(b*TT + t)*NMe*4;
            for (int i = tid; i < NMe*4; i += THREADS) {
                int m = i/4, k = i%4;
                s.xT[k*WX + 40 + m] = gm[i];
            }
            const int* ga = Xa_ex + (size_t)(b*TT + t)*NAq*4;
            for (int i = tid; i < NAq*4; i += THREADS) s.exa[i] = ga[i];
            const int* gme = Xm_ex + (size_t)(b*TT + t)*NMe*5;
            for (int i = tid; i < NMe*5; i += THREADS) s.exm[i] = gme[i];
        }
        __syncthreads();   // B1

        // p1: attri + featf, one 8-node tile per warp, f32x2 packed
        {
            u64 av[4] = {0,0,0,0}, fv[4] = {0,0,0,0};
            if (isA) {
                #pragma unroll
                for (int k = 0; k < 6; k++) {
                    ulonglong2 xa = *(const ulonglong2*)(s.xT + k*WX + cn0);
                    ulonglong2 xb = *(const ulonglong2*)(s.xT + k*WX + cn0 + 4);
                    u64 wa = dup2(s.Wxa[k*HH+lane]);
                    u64 wu = dup2(s.Wua[k*HH+lane]);
                    fma2(av[0], xa.x, wa); fma2(av[1], xa.y, wa);
                    fma2(av[2], xb.x, wa); fma2(av[3], xb.y, wa);
                    fma2(fv[0], xa.x, wu); fma2(fv[1], xa.y, wu);
                    fma2(fv[2], xb.x, wu); fma2(fv[3], xb.y, wu);
                }
                const int offs[4] = {0, 35, 48, 55};
                #pragma unroll
                for (int e = 0; e < 4; e++) {
                    u64 wA = dup2(s.Wua[(6+2*e)*HH+lane]);
                    u64 wB = dup2(s.Wua[(7+2*e)*HH+lane]);
                    #pragma unroll
                    for (int pr = 0; pr < 4; pr++) {
                        int n0 = cn0 + 2*pr, n1 = n0 + 1;
                        int i0 = (n0 < NAq) ? s.exa[n0*4+e] : 0;
                        int i1 = (n1 < NAq) ? s.exa[n1*4+e] : 0;
                        float2 em0 = *(const float2*)(s.emb_aqi + (offs[e]+i0)*2);
                        float2 em1 = *(const float2*)(s.emb_aqi + (offs[e]+i1)*2);
                        fma2(fv[pr], pk2(em0.x, em1.x), wA);
                        fma2(fv[pr], pk2(em0.y, em1.y), wB);
                    }
                }
                #pragma unroll
                for (int pr = 0; pr < 4; pr++) {
                    float2 a2 = up2(av[pr]);
                    int n0 = cn0 + 2*pr;
                    if (n0   < NAq) s.attri[n0*HH + lane]     = a2.x;
                    if (n0+1 < NAq) s.attri[(n0+1)*HH + lane] = a2.y;
                }
            } else {
                #pragma unroll
                for (int k = 0; k < 4; k++) {
                    ulonglong2 xa = *(const ulonglong2*)(s.xT + k*WX + cn0);
                    ulonglong2 xb = *(const ulonglong2*)(s.xT + k*WX + cn0 + 4);
                    u64 wa = dup2(s.Wxm[k*HH+lane]);
                    u64 wu = dup2(s.Wum[k*HH+lane]);
                    fma2(av[0], xa.x, wa); fma2(av[1], xa.y, wa);
                    fma2(av[2], xb.x, wa); fma2(av[3], xb.y, wa);
                    fma2(fv[0], xa.x, wu); fma2(fv[1], xa.y, wu);
                    fma2(fv[2], xb.x, wu); fma2(fv[3], xb.y, wu);
                }
                const int offs[5] = {0, 9, 27, 40, 47};
                #pragma unroll
                for (int e = 0; e < 5; e++) {
                    u64 wA = dup2(s.Wum[(4+2*e)*HH+lane]);
                    u64 wB = dup2(s.Wum[(5+2*e)*HH+lane]);
                    #pragma unroll
                    for (int pr = 0; pr < 4; pr++) {
                        int c0 = cn0 + 2*pr, c1 = c0 + 1;
                        int i0 = (c0 <= 57) ? s.exm[(c0-40)*5+e] : 0;
                        int i1 = (c1 <= 57) ? s.exm[(c1-40)*5+e] : 0;
                        float2 em0 = *(const float2*)(s.emb_meo + (offs[e]+i0)*2);
                        float2 em1 = *(const float2*)(s.emb_meo + (offs[e]+i1)*2);
                        fma2(fv[pr], pk2(em0.x, em1.x), wA);
                        fma2(fv[pr], pk2(em0.y, em1.y), wB);
                    }
                }
                #pragma unroll
                for (int pr = 0; pr < 4; pr++) {
                    float2 a2 = up2(av[pr]);
                    int c0 = cn0 + 2*pr;
                    if (c0   <= 57) s.attri[(c0-5)*HH + lane] = a2.x;
                    if (c0+1 <= 57) s.attri[(c0-4)*HH + lane] = a2.y;
                }
            }
            *(ulonglong2*)(s.gat_T + lane*WD2 + cn0)     = make_ulonglong2(fv[0], fv[1]);
            *(ulonglong2*)(s.gat_T + lane*WD2 + cn0 + 4) = make_ulonglong2(fv[2], fv[3]);
        }
        __syncthreads();   // B2

        // p2: src/dst projections; padded weight rows -> conflict-free broadcasts
        {
            int role = tid >> 6, q = tid & 63;
            bool valid = (q < NAq) || (q >= 40 && q < 58);
            int n = (q < NAq) ? q : q - 5;
            int c; float acc; const float* w;
            bool nA = q < NAq;
            if (role == 0)      { c = nA?0:2; w = s.a_src[c]; acc = valid ? s.ctxsA[n] : 0.f; }
            else if (role == 1) { c = nA?1:3; w = s.a_src[c]; acc = valid ? s.ctxsM[n] : 0.f; }
            else if (role == 2) { c = nA?0:1; w = s.a_dst[c]; acc = valid ? s.ctxdA[n] : 0.f; }
            else                { c = nA?2:3; w = s.a_dst[c]; acc = valid ? s.ctxdM[n] : 0.f; }
            #pragma unroll 8
            for (int k = 0; k < HH; k++) acc += s.gat_T[k*WD2 + (q < 58 ? q : 0)] * w[k];
            if (valid) {
                if (role == 0)      s.srcA[n] = acc;
                else if (role == 1) s.srcM[n] = acc;
                else if (role == 2) s.dstA[n] = acc;
                else                s.dstM[n] = acc;
            }
        }
        __syncthreads();   // B3 — everything below is warp-private

        // p3/4: logits + exp + sum (valid columns only; pads stay zero from init)
        {
            float sum = 0.f;
            if (sm_valid) {
                int i = (sm_cn < NAq) ? sm_cn : sm_cn - 5;
                float sAv = s.srcA[i], sMv = s.srcM[i];
                const float* dp = (i < NAq) ? s.dstA : s.dstM;
                for (int j = sm_sub; j < NN; j += 4) {
                    float x = ((j < NAq) ? sAv : sMv) + dp[j] + __ldg(g_baseT + j*SW + sm_cn);
                    x = (x >= 0.f) ? x : 0.2f*x;
                    float v = __expf(fminf(x, 60.f));
                    s.attT[j*SW+sm_cn] = v;
                    sum += v;
                }
            }
            sum += __shfl_xor_sync(0xffffffffu, sum, 1);
            sum += __shfl_xor_sync(0xffffffffu, sum, 2);
            if (sm_sub == 0 && sm_valid) s.inv[sm_cn] = __fdividef(1.f, sum);
        }
        __syncwarp();

        // p5: GAT output (att @ attri, f32x2), same-warp tile
        {
            u64 acc[4] = {0,0,0,0};
            #pragma unroll 4
            for (int j = 0; j < NN; j++) {
                u64 ap = dup2(s.attri[j*HH + lane]);
                ulonglong2 t0 = *(const ulonglong2*)(s.attT + j*SW + cn0);
                ulonglong2 t1 = *(const ulonglong2*)(s.attT + j*SW + cn0 + 4);
                fma2(acc[0], t0.x, ap); fma2(acc[1], t0.y, ap);
                fma2(acc[2], t1.x, ap); fma2(acc[3], t1.y, ap);
            }
            float4 iv0 = *(const float4*)(s.inv + cn0);
            float4 iv1 = *(const float4*)(s.inv + cn0 + 4);
            acc[0] = mul2(acc[0], pk2(iv0.x, iv0.y));
            acc[1] = mul2(acc[1], pk2(iv0.z, iv0.w));
            acc[2] = mul2(acc[2], pk2(iv1.x, iv1.y));
            acc[3] = mul2(acc[3], pk2(iv1.z, iv1.w));
            *(ulonglong2*)(s.gat_T + lane*WD2 + cn0)     = make_ulonglong2(acc[0], acc[1]);
            *(ulonglong2*)(s.gat_T + lane*WD2 + cn0 + 4) = make_ulonglong2(acc[2], acc[3]);
        }
        __syncwarp();

        // p6: GRU, same tile, f32x2; weights via per-lane float4 rows
        {
            u64 gr[4]={0,0,0,0}, gz[4]={0,0,0,0}, gn[4]={0,0,0,0};
            u64 hr[4]={0,0,0,0}, hz[4]={0,0,0,0}, hn[4]={0,0,0,0};
            #pragma unroll
            for (int kc = 0; kc < 8; kc++) {
                float4 W0 = *(const float4*)(WI + lane*GS + 4*kc);
                float4 W1 = *(const float4*)(WI + (32+lane)*GS + 4*kc);
                float4 W2 = *(const float4*)(WI + (64+lane)*GS + 4*kc);
                float4 V0 = *(const float4*)(WH + lane*GS + 4*kc);
                float4 V1 = *(const float4*)(WH + (32+lane)*GS + 4*kc);
                float4 V2 = *(const float4*)(WH + (64+lane)*GS + 4*kc);
                const float* w0p = (const float*)&W0;
                const float* w1p = (const float*)&W1;
                const float* w2p = (const float*)&W2;
                const float* v0p = (const float*)&V0;
                const float* v1p = (const float*)&V1;
                const float* v2p = (const float*)&V2;
                #pragma unroll
                for (int kk = 0; kk < 4; kk++) {
                    int k = 4*kc + kk;
                    ulonglong2 x0 = *(const ulonglong2*)(s.gat_T + k*WD2 + cn0);
                    ulonglong2 x1 = *(const ulonglong2*)(s.gat_T + k*WD2 + cn0 + 4);
                    ulonglong2 h0 = *(const ulonglong2*)(s.h_T  + k*WD2 + cn0);
                    ulonglong2 h1 = *(const ulonglong2*)(s.h_T  + k*WD2 + cn0 + 4);
                    u64 w0 = dup2(w0p[kk]);
                    u64 w1 = dup2(w1p[kk]);
                    u64 w2 = dup2(w2p[kk]);
                    u64 v0 = dup2(v0p[kk]);
                    u64 v1 = dup2(v1p[kk]);
                    u64 v2 = dup2(v2p[kk]);
                    fma2(gr[0], x0.x, w0); fma2(gr[1], x0.y, w0);
                    fma2(gr[2], x1.x, w0); fma2(gr[3], x1.y, w0);
                    fma2(gz[0], x0.x, w1); fma2(gz[1], x0.y, w1);
                    fma2(gz[2], x1.x, w1); fma2(gz[3], x1.y, w1);
                    fma2(gn[0], x0.x, w2); fma2(gn[1], x0.y, w2);
                    fma2(gn[2], x1.x, w2); fma2(gn[3], x1.y, w2);
                    fma2(hr[0], h0.x, v0); fma2(hr[1], h0.y, v0);
                    fma2(hr[2], h1.x, v0); fma2(hr[3], h1.y, v0);
                    fma2(hz[0], h0.x, v1); fma2(hz[1], h0.y, v1);
                    fma2(hz[2], h1.x, v1); fma2(hz[3], h1.y, v1);
                    fma2(hn[0], h0.x, v2); fma2(hn[1], h0.y, v2);
                    fma2(hn[2], h1.x, v2); fma2(hn[3], h1.y, v2);
                }
            }
            ulonglong2 ho0 = *(const ulonglong2*)(s.h_T + lane*WD2 + cn0);
            ulonglong2 ho1 = *(const ulonglong2*)(s.h_T + lane*WD2 + cn0 + 4);
            u64 hop[4] = {ho0.x, ho0.y, ho1.x, ho1.y};
            u64 res[4];
            #pragma unroll
            for (int p = 0; p < 4; p++) {
                float2 R = up2(gr[p]), Z = up2(gz[p]), Nn = up2(gn[p]);
                float2 HR = up2(hr[p]), HZ = up2(hz[p]), HN = up2(hn[p]);
                float2 HO = up2(hop[p]);
                float r0 = sigf(R.x + b_ir + HR.x + b_hr);
                float z0 = sigf(Z.x + b_iz + HZ.x + b_hz);
                float n0 = tanhf_fast(Nn.x + b_in + r0*(HN.x + b_hn));
                float o0 = (1.f - z0)*n0 + z0*HO.x;
                float r1 = sigf(R.y + b_ir + HR.y + b_hr);
                float z1 = sigf(Z.y + b_iz + HZ.y + b_hz);
                float n1 = tanhf_fast(Nn.y + b_in + r1*(HN.y + b_hn));
                float o1 = (1.f - z1)*n1 + z1*HO.y;
                res[p] = pk2(o0, o1);
            }
            __syncwarp();
            *(ulonglong2*)(s.h_T + lane*WD2 + cn0)     = make_ulonglong2(res[0], res[1]);
            *(ulonglong2*)(s.h_T + lane*WD2 + cn0 + 4) = make_ulonglong2(res[2], res[3]);
        }
    }

    // ---------- output ----------
    __syncthreads();
    for (int p = tid; p < NN*HH; p += THREADS) {
        int n = p >> 5, hd = p & 31;
        float v = s.h_T[hd*WD2 + CN(n)];
        if (n < NAq) out[((size_t)b*NAq + n)*HH + hd] = v;
        else         out[(size_t)NB*NAq*HH + ((size_t)b*NMe + (n-NAq))*HH + hd] = v;
    }
}

extern "C" void kernel_launch(void* const* d_in, const int* in_sizes, int n_in,
                              void* d_out, int out_size)
{
    (void)in_sizes; (void)n_in; (void)out_size;
    base_kernel<<<8, 256>>>(
        (const float*)d_in[3],  (const float*)d_in[4],
        (const float*)d_in[18], (const float*)d_in[19],
        (const float*)d_in[20], (const float*)d_in[21]);
    cudaFuncSetAttribute(chgat_gru_kernel,
                         cudaFuncAttributeMaxDynamicSharedMemorySize,
                         (int)sizeof(SM));
    chgat_gru_kernel<<<NB, THREADS, sizeof(SM)>>>(
        (const float*)d_in[0],  (const float*)d_in[1],
        (const float*)d_in[2],
        (const float*)d_in[5],  (const float*)d_in[6],
        (const float*)d_in[7],  (const float*)d_in[8],
        (const float*)d_in[9],  (const float*)d_in[10],
        (const float*)d_in[11], (const float*)d_in[12],
        (const float*)d_in[13],
        (const float*)d_in[14], (const float*)d_in[15],
        (const float*)d_in[16], (const float*)d_in[17],
        (const float*)d_in[18], (const float*)d_in[19],
        (const float*)d_in[20], (const float*)d_in[21],
        (const float*)d_in[22], (const float*)d_in[23],
        (const float*)d_in[24], (const float*)d_in[25],
        (const float*)d_in[26], (const float*)d_in[27],
        (const float*)d_in[28], (const float*)d_in[29],
        (const int*)d_in[30],   (const int*)d_in[31],
        (float*)d_out);
}

// round 16
// speedup vs baseline: 1.1623x; 1.0378x over previous
#include <cuda_runtime.h>

#define NB   1024
#define TT   48
#define NAq  35
#define NMe  18
#define NN   53
#define HH   32
#define CTXD 60
#define THREADS 256
#define WX   64     // xT row stride
#define WD2  68     // h_T / gat_T row stride
#define SW   60     // attT/baseT row stride
#define GS   36     // GRU weight row stride ([gate][k] padded)

#define CN(n) ((n) < NAq ? (n) : (n) + 5)

typedef unsigned long long u64;

__device__ float g_baseT[NN*SW];

struct __align__(16) SM {
    float attT[NN*SW + 8];      // +8 tail pad: tile-7 float4 overflow at j=52
    float h_T[HH*WD2];          // [hd][cn]
    float gat_T[HH*WD2];        // [hd][cn] featf then GAT output
    float xT[6*WX];             // [k][cn]
    float inv[WX];
    float wih_a[96*GS], whh_a[96*GS], wih_m[96*GS], whh_m[96*GS]; // [gate][k] pad GS
    float Wxa[6*HH], Wxm[4*HH], Wua[14*HH], Wum[14*HH];
    float a_src[4][HH], a_dst[4][HH];
    float bih_a[96], bhh_a[96], bih_m[96], bhh_m[96];
    float emb_aqi[158];
    float emb_meo[142];
    float attri[NN*HH];         // [node][hd]
    float srcA[NN], srcM[NN], dstA[NN], dstM[NN];
    float ctxsA[NN], ctxsM[NN], ctxdA[NN], ctxdM[NN];
    int   exa[NAq*4];
    int   exm[NMe*5];
};

__device__ __forceinline__ u64 pk2(float lo, float hi) {
    u64 r; asm("mov.b64 %0,{%1,%2};" : "=l"(r) : "f"(lo), "f"(hi)); return r;
}
__device__ __forceinline__ u64 dup2(float v) { return pk2(v, v); }
__device__ __forceinline__ float2 up2(u64 a) {
    float2 r; asm("mov.b64 {%0,%1},%2;" : "=f"(r.x), "=f"(r.y) : "l"(a)); return r;
}
__device__ __forceinline__ void fma2(u64& d, u64 a, u64 b) {
    asm("fma.rn.f32x2 %0,%1,%2,%0;" : "+l"(d) : "l"(a), "l"(b));
}
__device__ __forceinline__ u64 mul2(u64 a, u64 b) {
    u64 r; asm("mul.rn.f32x2 %0,%1,%2;" : "=l"(r) : "l"(a), "l"(b)); return r;
}
__device__ __forceinline__ float sigf(float x) {
    return __fdividef(1.f, 1.f + __expf(-x));
}
__device__ __forceinline__ float tanhf_fast(float x) {
    return 2.f * sigf(2.f * x) - 1.f;
}

__global__ void base_kernel(const float* __restrict__ adj, const float* __restrict__ adjn,
                            const float* __restrict__ a_aa, const float* __restrict__ a_am,
                            const float* __restrict__ a_ma, const float* __restrict__ a_mm)
{
    float aL[4] = {a_aa[184], a_am[184], a_ma[184], a_mm[184]};
    int idx = blockIdx.x * blockDim.x + threadIdx.x;
    for (int p = idx; p < NN*SW; p += gridDim.x * blockDim.x) {
        int j = p / SW, cn = p % SW;
        bool valid = (cn < NAq) || (cn >= 40 && cn < 58);
        float v = -1e30f;
        if (valid) {
            int i = (cn < NAq) ? cn : cn - 5;
            int c = ((i < NAq) ? 0 : 2) + ((j < NAq) ? 0 : 1);
            v = (adj[i*NN+j] > 0.f) ? adjn[i*NN+j]*aL[c] : -1e30f;
        }
        g_baseT[p] = v;
    }
}

__global__ __launch_bounds__(THREADS, 2)
void chgat_gru_kernel(
    const float* __restrict__ X_aqi, const float* __restrict__ X_meo,
    const float* __restrict__ ctx,
    const float* __restrict__ e_ai,  const float* __restrict__ e_amo,
    const float* __restrict__ e_awd, const float* __restrict__ e_ahr,
    const float* __restrict__ e_mw,  const float* __restrict__ e_mi,
    const float* __restrict__ e_mmo, const float* __restrict__ e_mwd,
    const float* __restrict__ e_mhr,
    const float* __restrict__ Wxa,   const float* __restrict__ Wxm,
    const float* __restrict__ Wua,   const float* __restrict__ Wum,
    const float* __restrict__ a_aa,  const float* __restrict__ a_am,
    const float* __restrict__ a_ma,  const float* __restrict__ a_mm,
    const float* __restrict__ gaw_ih, const float* __restrict__ gaw_hh,
    const float* __restrict__ gab_ih, const float* __restrict__ gab_hh,
    const float* __restrict__ gmw_ih, const float* __restrict__ gmw_hh,
    const float* __restrict__ gmb_ih, const float* __restrict__ gmb_hh,
    const int* __restrict__ Xa_ex,   const int* __restrict__ Xm_ex,
    float* __restrict__ out)
{
    extern __shared__ char smraw[];
    SM& s = *reinterpret_cast<SM*>(smraw);

    const int tid  = threadIdx.x;
    const int b    = blockIdx.x;
    const int lane = tid & 31;
    const int wid  = tid >> 5;

    // ---------- one-time setup ----------
    for (int i = tid; i < 6*HH;  i += THREADS) s.Wxa[i] = Wxa[i];
    for (int i = tid; i < 4*HH;  i += THREADS) s.Wxm[i] = Wxm[i];
    for (int i = tid; i < 14*HH; i += THREADS) { s.Wua[i] = Wua[i]; s.Wum[i] = Wum[i]; }
    for (int i = tid; i < 96*HH; i += THREADS) {
        int g = i >> 5, k = i & 31;
        s.wih_a[g*GS+k] = gaw_ih[i]; s.whh_a[g*GS+k] = gaw_hh[i];
        s.wih_m[g*GS+k] = gmw_ih[i]; s.whh_m[g*GS+k] = gmw_hh[i];
    }
    for (int i = tid; i < 96; i += THREADS) {
        s.bih_a[i] = gab_ih[i]; s.bhh_a[i] = gab_hh[i];
        s.bih_m[i] = gmb_ih[i]; s.bhh_m[i] = gmb_hh[i];
    }
    for (int i = tid; i < 4*HH; i += THREADS) {
        int c = i >> 5, k = i & 31;
        const float* a = (c==0)?a_aa:(c==1)?a_am:(c==2)?a_ma:a_mm;
        s.a_src[c][k] = a[k];
        s.a_dst[c][k] = a[92+k];
    }
    for (int i = tid; i < 70; i += THREADS) s.emb_aqi[i]      = e_ai[i];
    for (int i = tid; i < 26; i += THREADS) s.emb_aqi[70+i]   = e_amo[i];
    for (int i = tid; i < 14; i += THREADS) s.emb_aqi[96+i]   = e_awd[i];
    for (int i = tid; i < 48; i += THREADS) s.emb_aqi[110+i]  = e_ahr[i];
    for (int i = tid; i < 18; i += THREADS) s.emb_meo[i]      = e_mw[i];
    for (int i = tid; i < 36; i += THREADS) s.emb_meo[18+i]   = e_mi[i];
    for (int i = tid; i < 26; i += THREADS) s.emb_meo[54+i]   = e_mmo[i];
    for (int i = tid; i < 14; i += THREADS) s.emb_meo[80+i]   = e_mwd[i];
    for (int i = tid; i < 48; i += THREADS) s.emb_meo[94+i]   = e_mhr[i];
    for (int i = tid; i < HH*WD2; i += THREADS) s.h_T[i] = 0.f;
    for (int i = tid; i < 6*WX; i += THREADS) s.xT[i] = 0.f;
    if (tid < 8) s.attT[NN*SW + tid] = 0.f;
    __syncthreads();

    // context dots (role x node), once
    for (int p = tid; p < 4*NN; p += THREADS) {
        int n = p % NN, role = p / NN;
        int c;
        if (role == 0)      c = (n<NAq)?0:2;
        else if (role == 1) c = (n<NAq)?1:3;
        else if (role == 2) c = (n<NAq)?0:1;
        else                c = (n<NAq)?2:3;
        const float* a = (c==0)?a_aa:(c==1)?a_am:(c==2)?a_ma:a_mm;
        const float* w = (role < 2) ? (a + 32) : (a + 124);
        float acc = 0.f;
        #pragma unroll 4
        for (int k = 0; k < CTXD; k++) acc += ctx[n*CTXD+k]*w[k];
        if (role == 0)      s.ctxsA[n] = acc;
        else if (role == 1) s.ctxsM[n] = acc;
        else if (role == 2) s.ctxdA[n] = acc;
        else                s.ctxdM[n] = acc;
    }
    __syncthreads();

    const int  cn0 = wid * 8;
    const bool isA = (wid < 5);
    const float* WI = isA ? s.wih_a : s.wih_m;
    const float* WH = isA ? s.whh_a : s.whh_m;
    const float* BI = isA ? s.bih_a : s.bih_m;
    const float* BH = isA ? s.bhh_a : s.bhh_m;
    const float b_ir = BI[lane], b_iz = BI[32+lane], b_in = BI[64+lane];
    const float b_hr = BH[lane], b_hz = BH[32+lane], b_hn = BH[64+lane];
    const int sm_cn  = cn0 + (lane >> 2);
    const int sm_sub = lane & 3;
    const bool sm_valid = (sm_cn < NAq) || (sm_cn >= 40 && sm_cn < 58);

    // ---------- input prefetch (register stash, double-buffered in time) ----------
    float pfA, pfM; int piA, piM;
    {
        const float* gx = X_aqi + (size_t)(b*TT + 0)*NAq*6;
        pfA = (tid < NAq*6) ? gx[tid] : 0.f;
        const float* gm = X_meo + (size_t)(b*TT + 0)*NMe*4;
        pfM = (tid < NMe*4) ? gm[tid] : 0.f;
        const int* ga = Xa_ex + (size_t)(b*TT + 0)*NAq*4;
        piA = (tid < NAq*4) ? ga[tid] : 0;
        const int* gme = Xm_ex + (size_t)(b*TT + 0)*NMe*5;
        piM = (tid < NMe*5) ? gme[tid] : 0;
    }

    // ---------- timestep loop: 3 CTA barriers per step ----------
    for (int t = 0; t < TT; t++) {
        // p0: commit stashed inputs to smem (fast; no global latency at barrier)
        {
            if (tid < NAq*6) { int n = tid/6, k = tid%6; s.xT[k*WX + n] = pfA; }
            if (tid < NMe*4) { int m = tid/4, k = tid%4; s.xT[k*WX + 40 + m] = pfM; }
            if (tid < NAq*4) s.exa[tid] = piA;
            if (tid < NMe*5) s.exm[tid] = piM;
        }
        __syncthreads();   // B1

        // issue next step's global loads now; they complete during p1..p6
        if (t + 1 < TT) {
            const float* gx = X_aqi + (size_t)(b*TT + t + 1)*NAq*6;
            pfA = (tid < NAq*6) ? gx[tid] : 0.f;
            const float* gm = X_meo + (size_t)(b*TT + t + 1)*NMe*4;
            pfM = (tid < NMe*4) ? gm[tid] : 0.f;
            const int* ga = Xa_ex + (size_t)(b*TT + t + 1)*NAq*4;
            piA = (tid < NAq*4) ? ga[tid] : 0;
            const int* gme = Xm_ex + (size_t)(b*TT + t + 1)*NMe*5;
            piM = (tid < NMe*5) ? gme[tid] : 0;
        }

        // p1: attri + featf, one 8-node tile per warp, f32x2 packed
        {
            u64 av[4] = {0,0,0,0}, fv[4] = {0,0,0,0};
            if (isA) {
                #pragma unroll
                for (int k = 0; k < 6; k++) {
                    ulonglong2 xa = *(const ulonglong2*)(s.xT + k*WX + cn0);
                    ulonglong2 xb = *(const ulonglong2*)(s.xT + k*WX + cn0 + 4);
                    u64 wa = dup2(s.Wxa[k*HH+lane]);
                    u64 wu = dup2(s.Wua[k*HH+lane]);
                    fma2(av[0], xa.x, wa); fma2(av[1], xa.y, wa);
                    fma2(av[2], xb.x, wa); fma2(av[3], xb.y, wa);
                    fma2(fv[0], xa.x, wu); fma2(fv[1], xa.y, wu);
                    fma2(fv[2], xb.x, wu); fma2(fv[3], xb.y, wu);
                }
                const int offs[4] = {0, 35, 48, 55};
                #pragma unroll
                for (int e = 0; e < 4; e++) {
                    u64 wA = dup2(s.Wua[(6+2*e)*HH+lane]);
                    u64 wB = dup2(s.Wua[(7+2*e)*HH+lane]);
                    #pragma unroll
                    for (int pr = 0; pr < 4; pr++) {
                        int n0 = cn0 + 2*pr, n1 = n0 + 1;
                        int i0 = (n0 < NAq) ? s.exa[n0*4+e] : 0;
                        int i1 = (n1 < NAq) ? s.exa[n1*4+e] : 0;
                        float2 em0 = *(const float2*)(s.emb_aqi + (offs[e]+i0)*2);
                        float2 em1 = *(const float2*)(s.emb_aqi + (offs[e]+i1)*2);
                        fma2(fv[pr], pk2(em0.x, em1.x), wA);
                        fma2(fv[pr], pk2(em0.y, em1.y), wB);
                    }
                }
                #pragma unroll
                for (int pr = 0; pr < 4; pr++) {
                    float2 a2 = up2(av[pr]);
                    int n0 = cn0 + 2*pr;
                    if (n0   < NAq) s.attri[n0*HH + lane]     = a2.x;
                    if (n0+1 < NAq) s.attri[(n0+1)*HH + lane] = a2.y;
                }
            } else {
                #pragma unroll
                for (int k = 0; k < 4; k++) {
                    ulonglong2 xa = *(const ulonglong2*)(s.xT + k*WX + cn0);
                    ulonglong2 xb = *(const ulonglong2*)(s.xT + k*WX + cn0 + 4);
                    u64 wa = dup2(s.Wxm[k*HH+lane]);
                    u64 wu = dup2(s.Wum[k*HH+lane]);
                    fma2(av[0], xa.x, wa); fma2(av[1], xa.y, wa);
                    fma2(av[2], xb.x, wa); fma2(av[3], xb.y, wa);
                    fma2(fv[0], xa.x, wu); fma2(fv[1], xa.y, wu);
                    fma2(fv[2], xb.x, wu); fma2(fv[3], xb.y, wu);
                }
                const int offs[5] = {0, 9, 27, 40, 47};
                #pragma unroll
                for (int e = 0; e < 5; e++) {
                    u64 wA = dup2(s.Wum[(4+2*e)*HH+lane]);
                    u64 wB = dup2(s.Wum[(5+2*e)*HH+lane]);
                    #pragma unroll
                    for (int pr = 0; pr < 4; pr++) {
                        int c0 = cn0 + 2*pr, c1 = c0 + 1;
                        int i0 = (c0 <= 57) ? s.exm[(c0-40)*5+e] : 0;
                        int i1 = (c1 <= 57) ? s.exm[(c1-40)*5+e] : 0;
                        float2 em0 = *(const float2*)(s.emb_meo + (offs[e]+i0)*2);
                        float2 em1 = *(const float2*)(s.emb_meo + (offs[e]+i1)*2);
                        fma2(fv[pr], pk2(em0.x, em1.x), wA);
                        fma2(fv[pr], pk2(em0.y, em1.y), wB);
                    }
                }
                #pragma unroll
                for (int pr = 0; pr < 4; pr++) {
                    float2 a2 = up2(av[pr]);
                    int c0 = cn0 + 2*pr;
                    if (c0   <= 57) s.attri[(c0-5)*HH + lane] = a2.x;
                    if (c0+1 <= 57) s.attri[(c0-4)*HH + lane] = a2.y;
                }
            }
            *(ulonglong2*)(s.gat_T + lane*WD2 + cn0)     = make_ulonglong2(fv[0], fv[1]);
            *(ulonglong2*)(s.gat_T + lane*WD2 + cn0 + 4) = make_ulonglong2(fv[2], fv[3]);
        }
        __syncthreads();   // B2

        // p2: src/dst projections (role x column)
        {
            int role = tid >> 6, q = tid & 63;
            bool valid = (q < NAq) || (q >= 40 && q < 58);
            int n = (q < NAq) ? q : q - 5;
            int c; float acc; const float* w;
            bool nA = q < NAq;
            if (role == 0)      { c = nA?0:2; w = s.a_src[c]; acc = valid ? s.ctxsA[n] : 0.f; }
            else if (role == 1) { c = nA?1:3; w = s.a_src[c]; acc = valid ? s.ctxsM[n] : 0.f; }
            else if (role == 2) { c = nA?0:1; w = s.a_dst[c]; acc = valid ? s.ctxdA[n] : 0.f; }
            else                { c = nA?2:3; w = s.a_dst[c]; acc = valid ? s.ctxdM[n] : 0.f; }
            #pragma unroll 8
            for (int k = 0; k < HH; k++) acc += s.gat_T[k*WD2 + (q < 58 ? q : 0)] * w[k];
            if (valid) {
                if (role == 0)      s.srcA[n] = acc;
                else if (role == 1) s.srcM[n] = acc;
                else if (role == 2) s.dstA[n] = acc;
                else                s.dstM[n] = acc;
            }
        }
        __syncthreads();   // B3 — everything below is warp-private

        // p3/4: logits + exp + sum for THIS WARP'S tile columns (quad per column)
        {
            float sum = 0.f;
            if (sm_valid) {
                int i = (sm_cn < NAq) ? sm_cn : sm_cn - 5;
                float sAv = s.srcA[i], sMv = s.srcM[i];
                const float* dp = (i < NAq) ? s.dstA : s.dstM;
                for (int j = sm_sub; j < NN; j += 4) {
                    float x = ((j < NAq) ? sAv : sMv) + dp[j] + __ldg(g_baseT + j*SW + sm_cn);
                    x = (x >= 0.f) ? x : 0.2f*x;
                    float v = __expf(fminf(x, 60.f));
                    s.attT[j*SW+sm_cn] = v;
                    sum += v;
                }
            } else if (sm_cn < SW) {
                for (int j = sm_sub; j < NN; j += 4) s.attT[j*SW+sm_cn] = 0.f;
            }
            sum += __shfl_xor_sync(0xffffffffu, sum, 1);
            sum += __shfl_xor_sync(0xffffffffu, sum, 2);
            if (sm_sub == 0) s.inv[sm_cn] = sm_valid ? __fdividef(1.f, sum) : 0.f;
        }
        __syncwarp();

        // p5: GAT output (att @ attri, f32x2), same-warp tile
        {
            u64 acc[4] = {0,0,0,0};
            #pragma unroll 4
            for (int j = 0; j < NN; j++) {
                u64 ap = dup2(s.attri[j*HH + lane]);
                ulonglong2 t0 = *(const ulonglong2*)(s.attT + j*SW + cn0);
                ulonglong2 t1 = *(const ulonglong2*)(s.attT + j*SW + cn0 + 4);
                fma2(acc[0], t0.x, ap); fma2(acc[1], t0.y, ap);
                fma2(acc[2], t1.x, ap); fma2(acc[3], t1.y, ap);
            }
            float4 iv0 = *(const float4*)(s.inv + cn0);
            float4 iv1 = *(const float4*)(s.inv + cn0 + 4);
            acc[0] = mul2(acc[0], pk2(iv0.x, iv0.y));
            acc[1] = mul2(acc[1], pk2(iv0.z, iv0.w));
            acc[2] = mul2(acc[2], pk2(iv1.x, iv1.y));
            acc[3] = mul2(acc[3], pk2(iv1.z, iv1.w));
            *(ulonglong2*)(s.gat_T + lane*WD2 + cn0)     = make_ulonglong2(acc[0], acc[1]);
            *(ulonglong2*)(s.gat_T + lane*WD2 + cn0 + 4) = make_ulonglong2(acc[2], acc[3]);
        }
        __syncwarp();

        // p6: GRU, same tile, f32x2; weights via per-lane float4 rows
        {
            u64 gr[4]={0,0,0,0}, gz[4]={0,0,0,0}, gn[4]={0,0,0,0};
            u64 hr[4]={0,0,0,0}, hz[4]={0,0,0,0}, hn[4]={0,0,0,0};
            #pragma unroll
            for (int kc = 0; kc < 8; kc++) {
                float4 W0 = *(const float4*)(WI + lane*GS + 4*kc);
                float4 W1 = *(const float4*)(WI + (32+lane)*GS + 4*kc);
                float4 W2 = *(const float4*)(WI + (64+lane)*GS + 4*kc);
                float4 V0 = *(const float4*)(WH + lane*GS + 4*kc);
                float4 V1 = *(const float4*)(WH + (32+lane)*GS + 4*kc);
                float4 V2 = *(const float4*)(WH + (64+lane)*GS + 4*kc);
                const float* w0p = (const float*)&W0;
                const float* w1p = (const float*)&W1;
                const float* w2p = (const float*)&W2;
                const float* v0p = (const float*)&V0;
                const float* v1p = (const float*)&V1;
                const float* v2p = (const float*)&V2;
                #pragma unroll
                for (int kk = 0; kk < 4; kk++) {
                    int k = 4*kc + kk;
                    ulonglong2 x0 = *(const ulonglong2*)(s.gat_T + k*WD2 + cn0);
                    ulonglong2 x1 = *(const ulonglong2*)(s.gat_T + k*WD2 + cn0 + 4);
                    ulonglong2 h0 = *(const ulonglong2*)(s.h_T  + k*WD2 + cn0);
                    ulonglong2 h1 = *(const ulonglong2*)(s.h_T  + k*WD2 + cn0 + 4);
                    u64 w0 = dup2(w0p[kk]);
                    u64 w1 = dup2(w1p[kk]);
                    u64 w2 = dup2(w2p[kk]);
                    u64 v0 = dup2(v0p[kk]);
                    u64 v1 = dup2(v1p[kk]);
                    u64 v2 = dup2(v2p[kk]);
                    fma2(gr[0], x0.x, w0); fma2(gr[1], x0.y, w0);
                    fma2(gr[2], x1.x, w0); fma2(gr[3], x1.y, w0);
                    fma2(gz[0], x0.x, w1); fma2(gz[1], x0.y, w1);
                    fma2(gz[2], x1.x, w1); fma2(gz[3], x1.y, w1);
                    fma2(gn[0], x0.x, w2); fma2(gn[1], x0.y, w2);
                    fma2(gn[2], x1.x, w2); fma2(gn[3], x1.y, w2);
                    fma2(hr[0], h0.x, v0); fma2(hr[1], h0.y, v0);
                    fma2(hr[2], h1.x, v0); fma2(hr[3], h1.y, v0);
                    fma2(hz[0], h0.x, v1); fma2(hz[1], h0.y, v1);
                    fma2(hz[2], h1.x, v1); fma2(hz[3], h1.y, v1);
                    fma2(hn[0], h0.x, v2); fma2(hn[1], h0.y, v2);
                    fma2(hn[2], h1.x, v2); fma2(hn[3], h1.y, v2);
                }
            }
            ulonglong2 ho0 = *(const ulonglong2*)(s.h_T + lane*WD2 + cn0);
            ulonglong2 ho1 = *(const ulonglong2*)(s.h_T + lane*WD2 + cn0 + 4);
            u64 hop[4] = {ho0.x, ho0.y, ho1.x, ho1.y};
            u64 res[4];
            #pragma unroll
            for (int p = 0; p < 4; p++) {
                float2 R = up2(gr[p]), Z = up2(gz[p]), Nn = up2(gn[p]);
                float2 HR = up2(hr[p]), HZ = up2(hz[p]), HN = up2(hn[p]);
                float2 HO = up2(hop[p]);
                float r0 = sigf(R.x + b_ir + HR.x + b_hr);
                float z0 = sigf(Z.x + b_iz + HZ.x + b_hz);
                float n0 = tanhf_fast(Nn.x + b_in + r0*(HN.x + b_hn));
                float o0 = (1.f - z0)*n0 + z0*HO.x;
                float r1 = sigf(R.y + b_ir + HR.y + b_hr);
                float z1 = sigf(Z.y + b_iz + HZ.y + b_hz);
                float n1 = tanhf_fast(Nn.y + b_in + r1*(HN.y + b_hn));
                float o1 = (1.f - z1)*n1 + z1*HO.y;
                res[p] = pk2(o0, o1);
            }
            __syncwarp();
            *(ulonglong2*)(s.h_T + lane*WD2 + cn0)     = make_ulonglong2(res[0], res[1]);
            *(ulonglong2*)(s.h_T + lane*WD2 + cn0 + 4) = make_ulonglong2(res[2], res[3]);
        }
    }

    // ---------- output ----------
    __syncthreads();
    for (int p = tid; p < NN*HH; p += THREADS) {
        int n = p >> 5, hd = p & 31;
        float v = s.h_T[hd*WD2 + CN(n)];
        if (n < NAq) out[((size_t)b*NAq + n)*HH + hd] = v;
        else         out[(size_t)NB*NAq*HH + ((size_t)b*NMe + (n-NAq))*HH + hd] = v;
    }
}

extern "C" void kernel_launch(void* const* d_in, const int* in_sizes, int n_in,
                              void* d_out, int out_size)
{
    (void)in_sizes; (void)n_in; (void)out_size;
    base_kernel<<<8, 256>>>(
        (const float*)d_in[3],  (const float*)d_in[4],
        (const float*)d_in[18], (const float*)d_in[19],
        (const float*)d_in[20], (const float*)d_in[21]);
    cudaFuncSetAttribute(chgat_gru_kernel,
                         cudaFuncAttributeMaxDynamicSharedMemorySize,
                         (int)sizeof(SM));
    chgat_gru_kernel<<<NB, THREADS, sizeof(SM)>>>(
        (const float*)d_in[0],  (const float*)d_in[1],
        (const float*)d_in[2],
        (const float*)d_in[5],  (const float*)d_in[6],
        (const float*)d_in[7],  (const float*)d_in[8],
        (const float*)d_in[9],  (const float*)d_in[10],
        (const float*)d_in[11], (const float*)d_in[12],
        (const float*)d_in[13],
        (const float*)d_in[14], (const float*)d_in[15],
        (const float*)d_in[16], (const float*)d_in[17],
        (const float*)d_in[18], (const float*)d_in[19],
        (const float*)d_in[20], (const float*)d_in[21],
        (const float*)d_in[22], (const float*)d_in[23],
        (const float*)d_in[24], (const float*)d_in[25],
        (const float*)d_in[26], (const float*)d_in[27],
        (const float*)d_in[28], (const float*)d_in[29],
        (const int*)d_in[30],   (const int*)d_in[31],
        (float*)d_out);
}

// round 17
// speedup vs baseline: 1.1675x; 1.0045x over previous
#include <cuda_runtime.h>
#include <cuda_fp16.h>

#define NB   1024
#define TT   48
#define NAq  35
#define NMe  18
#define NN   53
#define HH   32
#define CTXD 60
#define THREADS 256
#define WX   64     // xT row stride
#define WD2  68     // h_T / gat_T row stride
#define SW   60     // attT/baseT row stride
#define GSH  40     // GRU half-weight row stride (halves; 80B rows, 16B aligned)

#define CN(n) ((n) < NAq ? (n) : (n) + 5)

typedef unsigned long long u64;

__device__ float g_baseT[NN*SW];

struct __align__(16) SM {
    float attT[NN*SW + 8];      // +8 tail pad: tile-7 float4 overflow at j=52
    float h_T[HH*WD2];          // [hd][cn]
    float gat_T[HH*WD2];        // [hd][cn] featf then GAT output
    float xT[6*WX];             // [k][cn]
    float inv[WX];
    __half wih_ah[96*GSH], whh_ah[96*GSH];  // [gate][k] fp16, pad GSH
    __half wih_mh[96*GSH], whh_mh[96*GSH];
    float Wxa[6*HH], Wxm[4*HH], Wua[14*HH], Wum[14*HH];
    float a_src[4][HH], a_dst[4][HH];
    float bih_a[96], bhh_a[96], bih_m[96], bhh_m[96];
    float emb_aqi[158];
    float emb_meo[142];
    float attri[NN*HH];         // [node][hd]
    float srcA[NN], srcM[NN], dstA[NN], dstM[NN];
    float ctxsA[NN], ctxsM[NN], ctxdA[NN], ctxdM[NN];
    int   exa[NAq*4];
    int   exm[NMe*5];
};

__device__ __forceinline__ u64 pk2(float lo, float hi) {
    u64 r; asm("mov.b64 %0,{%1,%2};" : "=l"(r) : "f"(lo), "f"(hi)); return r;
}
__device__ __forceinline__ u64 dup2(float v) { return pk2(v, v); }
__device__ __forceinline__ float2 up2(u64 a) {
    float2 r; asm("mov.b64 {%0,%1},%2;" : "=f"(r.x), "=f"(r.y) : "l"(a)); return r;
}
__device__ __forceinline__ void fma2(u64& d, u64 a, u64 b) {
    asm("fma.rn.f32x2 %0,%1,%2,%0;" : "+l"(d) : "l"(a), "l"(b));
}
__device__ __forceinline__ u64 mul2(u64 a, u64 b) {
    u64 r; asm("mul.rn.f32x2 %0,%1,%2;" : "=l"(r) : "l"(a), "l"(b)); return r;
}
__device__ __forceinline__ float sigf(float x) {
    return __fdividef(1.f, 1.f + __expf(-x));
}
__device__ __forceinline__ float tanhf_fast(float x) {
    return 2.f * sigf(2.f * x) - 1.f;
}

__global__ void base_kernel(const float* __restrict__ adj, const float* __restrict__ adjn,
                            const float* __restrict__ a_aa, const float* __restrict__ a_am,
                            const float* __restrict__ a_ma, const float* __restrict__ a_mm)
{
    float aL[4] = {a_aa[184], a_am[184], a_ma[184], a_mm[184]};
    int idx = blockIdx.x * blockDim.x + threadIdx.x;
    for (int p = idx; p < NN*SW; p += gridDim.x * blockDim.x) {
        int j = p / SW, cn = p % SW;
        bool valid = (cn < NAq) || (cn >= 40 && cn < 58);
        float v = -1e30f;
        if (valid) {
            int i = (cn < NAq) ? cn : cn - 5;
            int c = ((i < NAq) ? 0 : 2) + ((j < NAq) ? 0 : 1);
            v = (adj[i*NN+j] > 0.f) ? adjn[i*NN+j]*aL[c] : -1e30f;
        }
        g_baseT[p] = v;
    }
}

__global__ __launch_bounds__(THREADS, 2)
void chgat_gru_kernel(
    const float* __restrict__ X_aqi, const float* __restrict__ X_meo,
    const float* __restrict__ ctx,
    const float* __restrict__ e_ai,  const float* __restrict__ e_amo,
    const float* __restrict__ e_awd, const float* __restrict__ e_ahr,
    const float* __restrict__ e_mw,  const float* __restrict__ e_mi,
    const float* __restrict__ e_mmo, const float* __restrict__ e_mwd,
    const float* __restrict__ e_mhr,
    const float* __restrict__ Wxa,   const float* __restrict__ Wxm,
    const float* __restrict__ Wua,   const float* __restrict__ Wum,
    const float* __restrict__ a_aa,  const float* __restrict__ a_am,
    const float* __restrict__ a_ma,  const float* __restrict__ a_mm,
    const float* __restrict__ gaw_ih, const float* __restrict__ gaw_hh,
    const float* __restrict__ gab_ih, const float* __restrict__ gab_hh,
    const float* __restrict__ gmw_ih, const float* __restrict__ gmw_hh,
    const float* __restrict__ gmb_ih, const float* __restrict__ gmb_hh,
    const int* __restrict__ Xa_ex,   const int* __restrict__ Xm_ex,
    float* __restrict__ out)
{
    extern __shared__ char smraw[];
    SM& s = *reinterpret_cast<SM*>(smraw);

    const int tid  = threadIdx.x;
    const int b    = blockIdx.x;
    const int lane = tid & 31;
    const int wid  = tid >> 5;

    // ---------- one-time setup ----------
    for (int i = tid; i < 6*HH;  i += THREADS) s.Wxa[i] = Wxa[i];
    for (int i = tid; i < 4*HH;  i += THREADS) s.Wxm[i] = Wxm[i];
    for (int i = tid; i < 14*HH; i += THREADS) { s.Wua[i] = Wua[i]; s.Wum[i] = Wum[i]; }
    for (int i = tid; i < 96*HH; i += THREADS) {
        int g = i >> 5, k = i & 31;
        s.wih_ah[g*GSH+k] = __float2half(gaw_ih[i]);
        s.whh_ah[g*GSH+k] = __float2half(gaw_hh[i]);
        s.wih_mh[g*GSH+k] = __float2half(gmw_ih[i]);
        s.whh_mh[g*GSH+k] = __float2half(gmw_hh[i]);
    }
    for (int i = tid; i < 96; i += THREADS) {
        s.bih_a[i] = gab_ih[i]; s.bhh_a[i] = gab_hh[i];
        s.bih_m[i] = gmb_ih[i]; s.bhh_m[i] = gmb_hh[i];
    }
    for (int i = tid; i < 4*HH; i += THREADS) {
        int c = i >> 5, k = i & 31;
        const float* a = (c==0)?a_aa:(c==1)?a_am:(c==2)?a_ma:a_mm;
        s.a_src[c][k] = a[k];
        s.a_dst[c][k] = a[92+k];
    }
    for (int i = tid; i < 70; i += THREADS) s.emb_aqi[i]      = e_ai[i];
    for (int i = tid; i < 26; i += THREADS) s.emb_aqi[70+i]   = e_amo[i];
    for (int i = tid; i < 14; i += THREADS) s.emb_aqi[96+i]   = e_awd[i];
    for (int i = tid; i < 48; i += THREADS) s.emb_aqi[110+i]  = e_ahr[i];
    for (int i = tid; i < 18; i += THREADS) s.emb_meo[i]      = e_mw[i];
    for (int i = tid; i < 36; i += THREADS) s.emb_meo[18+i]   = e_mi[i];
    for (int i = tid; i < 26; i += THREADS) s.emb_meo[54+i]   = e_mmo[i];
    for (int i = tid; i < 14; i += THREADS) s.emb_meo[80+i]   = e_mwd[i];
    for (int i = tid; i < 48; i += THREADS) s.emb_meo[94+i]   = e_mhr[i];
    for (int i = tid; i < HH*WD2; i += THREADS) s.h_T[i] = 0.f;
    for (int i = tid; i < 6*WX; i += THREADS) s.xT[i] = 0.f;
    if (tid < 8) s.attT[NN*SW + tid] = 0.f;
    __syncthreads();

    // context dots (role x node), once
    for (int p = tid; p < 4*NN; p += THREADS) {
        int n = p % NN, role = p / NN;
        int c;
        if (role == 0)      c = (n<NAq)?0:2;
        else if (role == 1) c = (n<NAq)?1:3;
        else if (role == 2) c = (n<NAq)?0:1;
        else                c = (n<NAq)?2:3;
        const float* a = (c==0)?a_aa:(c==1)?a_am:(c==2)?a_ma:a_mm;
        const float* w = (role < 2) ? (a + 32) : (a + 124);
        float acc = 0.f;
        #pragma unroll 4
        for (int k = 0; k < CTXD; k++) acc += ctx[n*CTXD+k]*w[k];
        if (role == 0)      s.ctxsA[n] = acc;
        else if (role == 1) s.ctxsM[n] = acc;
        else if (role == 2) s.ctxdA[n] = acc;
        else                s.ctxdM[n] = acc;
    }
    __syncthreads();

    const int  cn0 = wid * 8;
    const bool isA = (wid < 5);
    const __half* WIh = isA ? s.wih_ah : s.wih_mh;
    const __half* WHh = isA ? s.whh_ah : s.whh_mh;
    const float* BI = isA ? s.bih_a : s.bih_m;
    const float* BH = isA ? s.bhh_a : s.bhh_m;
    const float b_ir = BI[lane], b_iz = BI[32+lane], b_in = BI[64+lane];
    const float b_hr = BH[lane], b_hz = BH[32+lane], b_hn = BH[64+lane];
    const int sm_cn  = cn0 + (lane >> 2);
    const int sm_sub = lane & 3;
    const bool sm_valid = (sm_cn < NAq) || (sm_cn >= 40 && sm_cn < 58);

    // ---------- input prefetch (register stash, double-buffered in time) ----------
    float pfA, pfM; int piA, piM;
    {
        const float* gx = X_aqi + (size_t)(b*TT + 0)*NAq*6;
        pfA = (tid < NAq*6) ? gx[tid] : 0.f;
        const float* gm = X_meo + (size_t)(b*TT + 0)*NMe*4;
        pfM = (tid < NMe*4) ? gm[tid] : 0.f;
        const int* ga = Xa_ex + (size_t)(b*TT + 0)*NAq*4;
        piA = (tid < NAq*4) ? ga[tid] : 0;
        const int* gme = Xm_ex + (size_t)(b*TT + 0)*NMe*5;
        piM = (tid < NMe*5) ? gme[tid] : 0;
    }

    // ---------- timestep loop: 3 CTA barriers per step ----------
    for (int t = 0; t < TT; t++) {
        // p0: commit stashed inputs to smem
        {
            if (tid < NAq*6) { int n = tid/6, k = tid%6; s.xT[k*WX + n] = pfA; }
            if (tid < NMe*4) { int m = tid/4, k = tid%4; s.xT[k*WX + 40 + m] = pfM; }
            if (tid < NAq*4) s.exa[tid] = piA;
            if (tid < NMe*5) s.exm[tid] = piM;
        }
        __syncthreads();   // B1

        // issue next step's global loads now; they complete during p1..p6
        if (t + 1 < TT) {
            const float* gx = X_aqi + (size_t)(b*TT + t + 1)*NAq*6;
            pfA = (tid < NAq*6) ? gx[tid] : 0.f;
            const float* gm = X_meo + (size_t)(b*TT + t + 1)*NMe*4;
            pfM = (tid < NMe*4) ? gm[tid] : 0.f;
            const int* ga = Xa_ex + (size_t)(b*TT + t + 1)*NAq*4;
            piA = (tid < NAq*4) ? ga[tid] : 0;
            const int* gme = Xm_ex + (size_t)(b*TT + t + 1)*NMe*5;
            piM = (tid < NMe*5) ? gme[tid] : 0;
        }

        // p1: attri + featf, one 8-node tile per warp, f32x2 packed
        {
            u64 av[4] = {0,0,0,0}, fv[4] = {0,0,0,0};
            if (isA) {
                #pragma unroll
                for (int k = 0; k < 6; k++) {
                    ulonglong2 xa = *(const ulonglong2*)(s.xT + k*WX + cn0);
                    ulonglong2 xb = *(const ulonglong2*)(s.xT + k*WX + cn0 + 4);
                    u64 wa = dup2(s.Wxa[k*HH+lane]);
                    u64 wu = dup2(s.Wua[k*HH+lane]);
                    fma2(av[0], xa.x, wa); fma2(av[1], xa.y, wa);
                    fma2(av[2], xb.x, wa); fma2(av[3], xb.y, wa);
                    fma2(fv[0], xa.x, wu); fma2(fv[1], xa.y, wu);
                    fma2(fv[2], xb.x, wu); fma2(fv[3], xb.y, wu);
                }
                const int offs[4] = {0, 35, 48, 55};
                #pragma unroll
                for (int e = 0; e < 4; e++) {
                    u64 wA = dup2(s.Wua[(6+2*e)*HH+lane]);
                    u64 wB = dup2(s.Wua[(7+2*e)*HH+lane]);
                    #pragma unroll
                    for (int pr = 0; pr < 4; pr++) {
                        int n0 = cn0 + 2*pr, n1 = n0 + 1;
                        int i0 = (n0 < NAq) ? s.exa[n0*4+e] : 0;
                        int i1 = (n1 < NAq) ? s.exa[n1*4+e] : 0;
                        float2 em0 = *(const float2*)(s.emb_aqi + (offs[e]+i0)*2);
                        float2 em1 = *(const float2*)(s.emb_aqi + (offs[e]+i1)*2);
                        fma2(fv[pr], pk2(em0.x, em1.x), wA);
                        fma2(fv[pr], pk2(em0.y, em1.y), wB);
                    }
                }
                #pragma unroll
                for (int pr = 0; pr < 4; pr++) {
                    float2 a2 = up2(av[pr]);
                    int n0 = cn0 + 2*pr;
                    if (n0   < NAq) s.attri[n0*HH + lane]     = a2.x;
                    if (n0+1 < NAq) s.attri[(n0+1)*HH + lane] = a2.y;
                }
            } else {
                #pragma unroll
                for (int k = 0; k < 4; k++) {
                    ulonglong2 xa = *(const ulonglong2*)(s.xT + k*WX + cn0);
                    ulonglong2 xb = *(const ulonglong2*)(s.xT + k*WX + cn0 + 4);
                    u64 wa = dup2(s.Wxm[k*HH+lane]);
                    u64 wu = dup2(s.Wum[k*HH+lane]);
                    fma2(av[0], xa.x, wa); fma2(av[1], xa.y, wa);
                    fma2(av[2], xb.x, wa); fma2(av[3], xb.y, wa);
                    fma2(fv[0], xa.x, wu); fma2(fv[1], xa.y, wu);
                    fma2(fv[2], xb.x, wu); fma2(fv[3], xb.y, wu);
                }
                const int offs[5] = {0, 9, 27, 40, 47};
                #pragma unroll
                for (int e = 0; e < 5; e++) {
                    u64 wA = dup2(s.Wum[(4+2*e)*HH+lane]);
                    u64 wB = dup2(s.Wum[(5+2*e)*HH+lane]);
                    #pragma unroll
                    for (int pr = 0; pr < 4; pr++) {
                        int c0 = cn0 + 2*pr, c1 = c0 + 1;
                        int i0 = (c0 <= 57) ? s.exm[(c0-40)*5+e] : 0;
                        int i1 = (c1 <= 57) ? s.exm[(c1-40)*5+e] : 0;
                        float2 em0 = *(const float2*)(s.emb_meo + (offs[e]+i0)*2);
                        float2 em1 = *(const float2*)(s.emb_meo + (offs[e]+i1)*2);
                        fma2(fv[pr], pk2(em0.x, em1.x), wA);
                        fma2(fv[pr], pk2(em0.y, em1.y), wB);
                    }
                }
                #pragma unroll
                for (int pr = 0; pr < 4; pr++) {
                    float2 a2 = up2(av[pr]);
                    int c0 = cn0 + 2*pr;
                    if (c0   <= 57) s.attri[(c0-5)*HH + lane] = a2.x;
                    if (c0+1 <= 57) s.attri[(c0-4)*HH + lane] = a2.y;
                }
            }
            *(ulonglong2*)(s.gat_T + lane*WD2 + cn0)     = make_ulonglong2(fv[0], fv[1]);
            *(ulonglong2*)(s.gat_T + lane*WD2 + cn0 + 4) = make_ulonglong2(fv[2], fv[3]);
        }
        __syncthreads();   // B2

        // p2: src/dst projections (role x column)
        {
            int role = tid >> 6, q = tid & 63;
            bool valid = (q < NAq) || (q >= 40 && q < 58);
            int n = (q < NAq) ? q : q - 5;
            int c; float acc; const float* w;
            bool nA = q < NAq;
            if (role == 0)      { c = nA?0:2; w = s.a_src[c]; acc = valid ? s.ctxsA[n] : 0.f; }
            else if (role == 1) { c = nA?1:3; w = s.a_src[c]; acc = valid ? s.ctxsM[n] : 0.f; }
            else if (role == 2) { c = nA?0:1; w = s.a_dst[c]; acc = valid ? s.ctxdA[n] : 0.f; }
            else                { c = nA?2:3; w = s.a_dst[c]; acc = valid ? s.ctxdM[n] : 0.f; }
            #pragma unroll 8
            for (int k = 0; k < HH; k++) acc += s.gat_T[k*WD2 + (q < 58 ? q : 0)] * w[k];
            if (valid) {
                if (role == 0)      s.srcA[n] = acc;
                else if (role == 1) s.srcM[n] = acc;
                else if (role == 2) s.dstA[n] = acc;
                else                s.dstM[n] = acc;
            }
        }
        __syncthreads();   // B3 — everything below is warp-private

        // p3/4: logits + exp + sum for THIS WARP'S tile columns (quad per column)
        {
            float sum = 0.f;
            if (sm_valid) {
                int i = (sm_cn < NAq) ? sm_cn : sm_cn - 5;
                float sAv = s.srcA[i], sMv = s.srcM[i];
                const float* dp = (i < NAq) ? s.dstA : s.dstM;
                for (int j = sm_sub; j < NN; j += 4) {
                    float x = ((j < NAq) ? sAv : sMv) + dp[j] + __ldg(g_baseT + j*SW + sm_cn);
                    x = (x >= 0.f) ? x : 0.2f*x;
                    float v = __expf(fminf(x, 60.f));
                    s.attT[j*SW+sm_cn] = v;
                    sum += v;
                }
            } else if (sm_cn < SW) {
                for (int j = sm_sub; j < NN; j += 4) s.attT[j*SW+sm_cn] = 0.f;
            }
            sum += __shfl_xor_sync(0xffffffffu, sum, 1);
            sum += __shfl_xor_sync(0xffffffffu, sum, 2);
            if (sm_sub == 0) s.inv[sm_cn] = sm_valid ? __fdividef(1.f, sum) : 0.f;
        }
        __syncwarp();

        // p5: GAT output (att @ attri, f32x2), same-warp tile
        {
            u64 acc[4] = {0,0,0,0};
            #pragma unroll 4
            for (int j = 0; j < NN; j++) {
                u64 ap = dup2(s.attri[j*HH + lane]);
                ulonglong2 t0 = *(const ulonglong2*)(s.attT + j*SW + cn0);
                ulonglong2 t1 = *(const ulonglong2*)(s.attT + j*SW + cn0 + 4);
                fma2(acc[0], t0.x, ap); fma2(acc[1], t0.y, ap);
                fma2(acc[2], t1.x, ap); fma2(acc[3], t1.y, ap);
            }
            float4 iv0 = *(const float4*)(s.inv + cn0);
            float4 iv1 = *(const float4*)(s.inv + cn0 + 4);
            acc[0] = mul2(acc[0], pk2(iv0.x, iv0.y));
            acc[1] = mul2(acc[1], pk2(iv0.z, iv0.w));
            acc[2] = mul2(acc[2], pk2(iv1.x, iv1.y));
            acc[3] = mul2(acc[3], pk2(iv1.z, iv1.w));
            *(ulonglong2*)(s.gat_T + lane*WD2 + cn0)     = make_ulonglong2(acc[0], acc[1]);
            *(ulonglong2*)(s.gat_T + lane*WD2 + cn0 + 4) = make_ulonglong2(acc[2], acc[3]);
        }
        __syncwarp();

        // p6: GRU, same tile, f32x2; fp16 weights via per-lane uint4 rows (8 k per load)
        {
            u64 gr[4]={0,0,0,0}, gz[4]={0,0,0,0}, gn[4]={0,0,0,0};
            u64 hr[4]={0,0,0,0}, hz[4]={0,0,0,0}, hn[4]={0,0,0,0};
            #pragma unroll
            for (int kc = 0; kc < 4; kc++) {
                uint4 W0 = *(const uint4*)(WIh + lane*GSH + 8*kc);
                uint4 W1 = *(const uint4*)(WIh + (32+lane)*GSH + 8*kc);
                uint4 W2 = *(const uint4*)(WIh + (64+lane)*GSH + 8*kc);
                uint4 V0 = *(const uint4*)(WHh + lane*GSH + 8*kc);
                uint4 V1 = *(const uint4*)(WHh + (32+lane)*GSH + 8*kc);
                uint4 V2 = *(const uint4*)(WHh + (64+lane)*GSH + 8*kc);
                const __half* w0p = (const __half*)&W0;
                const __half* w1p = (const __half*)&W1;
                const __half* w2p = (const __half*)&W2;
                const __half* v0p = (const __half*)&V0;
                const __half* v1p = (const __half*)&V1;
                const __half* v2p = (const __half*)&V2;
                #pragma unroll
                for (int kk = 0; kk < 8; kk++) {
                    int k = 8*kc + kk;
                    ulonglong2 x0 = *(const ulonglong2*)(s.gat_T + k*WD2 + cn0);
                    ulonglong2 x1 = *(const ulonglong2*)(s.gat_T + k*WD2 + cn0 + 4);
                    ulonglong2 h0 = *(const ulonglong2*)(s.h_T  + k*WD2 + cn0);
                    ulonglong2 h1 = *(const ulonglong2*)(s.h_T  + k*WD2 + cn0 + 4);
                    u64 w0 = dup2(__half2float(w0p[kk]));
                    u64 w1 = dup2(__half2float(w1p[kk]));
                    u64 w2 = dup2(__half2float(w2p[kk]));
                    u64 v0 = dup2(__half2float(v0p[kk]));
                    u64 v1 = dup2(__half2float(v1p[kk]));
                    u64 v2 = dup2(__half2float(v2p[kk]));
                    fma2(gr[0], x0.x, w0); fma2(gr[1], x0.y, w0);
                    fma2(gr[2], x1.x, w0); fma2(gr[3], x1.y, w0);
                    fma2(gz[0], x0.x, w1); fma2(gz[1], x0.y, w1);
                    fma2(gz[2], x1.x, w1); fma2(gz[3], x1.y, w1);
                    fma2(gn[0], x0.x, w2); fma2(gn[1], x0.y, w2);
                    fma2(gn[2], x1.x, w2); fma2(gn[3], x1.y, w2);
                    fma2(hr[0], h0.x, v0); fma2(hr[1], h0.y, v0);
                    fma2(hr[2], h1.x, v0); fma2(hr[3], h1.y, v0);
                    fma2(hz[0], h0.x, v1); fma2(hz[1], h0.y, v1);
                    fma2(hz[2], h1.x, v1); fma2(hz[3], h1.y, v1);
                    fma2(hn[0], h0.x, v2); fma2(hn[1], h0.y, v2);
                    fma2(hn[2], h1.x, v2); fma2(hn[3], h1.y, v2);
                }
            }
            ulonglong2 ho0 = *(const ulonglong2*)(s.h_T + lane*WD2 + cn0);
            ulonglong2 ho1 = *(const ulonglong2*)(s.h_T + lane*WD2 + cn0 + 4);
            u64 hop[4] = {ho0.x, ho0.y, ho1.x, ho1.y};
            u64 res[4];
            #pragma unroll
            for (int p = 0; p < 4; p++) {
                float2 R = up2(gr[p]), Z = up2(gz[p]), Nn = up2(gn[p]);
                float2 HR = up2(hr[p]), HZ = up2(hz[p]), HN = up2(hn[p]);
                float2 HO = up2(hop[p]);
                float r0 = sigf(R.x + b_ir + HR.x + b_hr);
                float z0 = sigf(Z.x + b_iz + HZ.x + b_hz);
                float n0 = tanhf_fast(Nn.x + b_in + r0*(HN.x + b_hn));
                float o0 = (1.f - z0)*n0 + z0*HO.x;
                float r1 = sigf(R.y + b_ir + HR.y + b_hr);
                float z1 = sigf(Z.y + b_iz + HZ.y + b_hz);
                float n1 = tanhf_fast(Nn.y + b_in + r1*(HN.y + b_hn));
                float o1 = (1.f - z1)*n1 + z1*HO.y;
                res[p] = pk2(o0, o1);
            }
            __syncwarp();
            *(ulonglong2*)(s.h_T + lane*WD2 + cn0)     = make_ulonglong2(res[0], res[1]);
            *(ulonglong2*)(s.h_T + lane*WD2 + cn0 + 4) = make_ulonglong2(res[2], res[3]);
        }
    }

    // ---------- output ----------
    __syncthreads();
    for (int p = tid; p < NN*HH; p += THREADS) {
        int n = p >> 5, hd = p & 31;
        float v = s.h_T[hd*WD2 + CN(n)];
        if (n < NAq) out[((size_t)b*NAq + n)*HH + hd] = v;
        else         out[(size_t)NB*NAq*HH + ((size_t)b*NMe + (n-NAq))*HH + hd] = v;
    }
}

extern "C" void kernel_launch(void* const* d_in, const int* in_sizes, int n_in,
                              void* d_out, int out_size)
{
    (void)in_sizes; (void)n_in; (void)out_size;
    base_kernel<<<8, 256>>>(
        (const float*)d_in[3],  (const float*)d_in[4],
        (const float*)d_in[18], (const float*)d_in[19],
        (const float*)d_in[20], (const float*)d_in[21]);
    cudaFuncSetAttribute(chgat_gru_kernel,
                         cudaFuncAttributeMaxDynamicSharedMemorySize,
                         (int)sizeof(SM));
    chgat_gru_kernel<<<NB, THREADS, sizeof(SM)>>>(
        (const float*)d_in[0],  (const float*)d_in[1],
        (const float*)d_in[2],
        (const float*)d_in[5],  (const float*)d_in[6],
        (const float*)d_in[7],  (const float*)d_in[8],
        (const float*)d_in[9],  (const float*)d_in[10],
        (const float*)d_in[11], (const float*)d_in[12],
        (const float*)d_in[13],
        (const float*)d_in[14], (const float*)d_in[15],
        (const float*)d_in[16], (const float*)d_in[17],
        (const float*)d_in[18], (const float*)d_in[19],
        (const float*)d_in[20], (const float*)d_in[21],
        (const float*)d_in[22], (const float*)d_in[23],
        (const float*)d_in[24], (const float*)d_in[25],
        (const float*)d_in[26], (const float*)d_in[27],
        (const float*)d_in[28], (const float*)d_in[29],
        (const int*)d_in[30],   (const int*)d_in[31],
        (float*)d_out);
}